// round 10
// baseline (speedup 1.0000x reference)
#include <cuda_runtime.h>
#include <stdint.h>
#include <stddef.h>

#define N0   32768
#define NP1  2048
#define NS1  32
#define NP2  512
#define NS2  64

// ---------------- static scratch (no runtime allocation allowed) ----------------
__device__ float4 g_xyz[N0];
__device__ float  g_feats[N0 * 12];
__device__ float4 g_newxyz1[NP1];
__device__ int    g_gidx1[NP1 * NS1];
__device__ float  g_h0[NP1 * NS1 * 16];            // SA1 L0 input, K 15->16
__device__ float  g_bufA[65536 * 64];              // 16 MB
__device__ float  g_bufB[65536 * 64];              // 16 MB
__device__ float  g_bufC[65536 * 128];             // 32 MB
__device__ float  g_bufD[32768 * 256];             // 32 MB
__device__ float  g_f1[NP1 * 128];
__device__ float4 g_newxyz2[NP2];
__device__ int    g_gidx2[NP2 * NS2];
__device__ float  g_f2[NP2 * 256];
__device__ float  g_a3[NP2 * 272];                 // SA3 input, K 259->272
__device__ float  g_wp[64*16 + 128*144 + 256*272]; // padded weights

#define WP1_OFF 0
#define WP2_OFF (64*16)
#define WP3_OFF (64*16 + 128*144)

// ---------------- helpers ----------------
// square-then-add (no FMA) to mirror XLA's elementwise (x-c)**2 then reduce
__device__ __forceinline__ float sqdist(float px, float py, float pz,
                                        float cx, float cy, float cz) {
    float dx = __fsub_rn(px, cx), dy = __fsub_rn(py, cy), dz = __fsub_rn(pz, cz);
    return __fadd_rn(__fadd_rn(__fmul_rn(dx, dx), __fmul_rn(dy, dy)), __fmul_rn(dz, dz));
}
// warp argmax over non-negative floats (bits order-isomorphic), tie -> min index.
__device__ __forceinline__ void warp_argmax(unsigned vbits, unsigned idx,
                                            unsigned& maxbits, unsigned& minidx) {
    maxbits = __reduce_max_sync(0xffffffffu, vbits);
    minidx  = __reduce_min_sync(0xffffffffu, (vbits == maxbits) ? idx : 0xffffffffu);
}
__device__ __forceinline__ uint32_t smem_u32(const void* p) {
    uint32_t a;
    asm("{ .reg .u64 t; cvta.to.shared.u64 t, %1; cvt.u32.u64 %0, t; }" : "=r"(a) : "l"(p));
    return a;
}
__device__ __forceinline__ uint32_t mapa_cluster(uint32_t laddr, uint32_t rank) {
    uint32_t r;
    asm("mapa.shared::cluster.u32 %0, %1, %2;" : "=r"(r) : "r"(laddr), "r"(rank));
    return r;
}
__device__ __forceinline__ void st_cluster_u64(uint32_t addr, unsigned long long v) {
    asm volatile("st.shared::cluster.u64 [%0], %1;" :: "r"(addr), "l"(v) : "memory");
}
__device__ __forceinline__ unsigned long long ldv_sh_u64(uint32_t addr) {
    unsigned long long v;
    asm volatile("ld.volatile.shared.u64 %0, [%1];" : "=l"(v) : "r"(addr));
    return v;
}

// ---------------- stage 0: xyz + feats ----------------
__global__ void prep_kernel(const float* __restrict__ pts, const float* __restrict__ prop) {
    int i = blockIdx.x * blockDim.x + threadIdx.x;
    if (i >= N0) return;
    float x = prop[0], y = prop[1], w = prop[3];
    float hw = __fmul_rn(w, 0.5f);
    float px = pts[i * 3 + 0], py = pts[i * 3 + 1], pz = pts[i * 3 + 2];
    float ax = __fsub_rn(px, x), ay = __fsub_rn(py, y);
    g_xyz[i] = make_float4(ax, ay, pz, 0.f);
    float oxp = __fadd_rn(x, hw), oxm = __fsub_rn(x, hw);
    float oyp = __fadd_rn(y, hw), oym = __fsub_rn(y, hw);
    float* f = &g_feats[(size_t)i * 12];
    f[0] = __fsub_rn(px, oxp); f[1]  = ay;                 f[2]  = pz;
    f[3] = __fsub_rn(px, oxm); f[4]  = ay;                 f[5]  = pz;
    f[6] = ax;                 f[7]  = __fsub_rn(py, oyp); f[8]  = pz;
    f[9] = ax;                 f[10] = __fsub_rn(py, oym); f[11] = pz;
}

// ------ FPS1: 8-CTA cluster, DSMEM mailbox exchange, smem handshakes, no barriers
// per-iteration. Each u64 word is self-tagged (tag <= 2047 fits 16 bits; point
// idx < 32768 fits 15 bits) -> 8B volatile/DSMEM stores are atomic, no fences
// needed for slot/mailbox. sres uses data -> membar.cta -> tag.
__global__ void __launch_bounds__(1024) __cluster_dims__(8, 1, 1)
fps1_kernel() {
    extern __shared__ float4 sxyz[];                       // 4096 pts = 64KB dynamic
    __shared__ volatile unsigned long long slot[2][32];    // per-warp partials
    __shared__ unsigned long long mbox[2][8][4];           // per-src-CTA packets
    __shared__ volatile float sresx[2], sresy[2], sresz[2];
    __shared__ volatile unsigned srestag[2];

    const int b = blockIdx.x;                              // == cluster rank
    const int t = threadIdx.x;
    const int lane = t & 31, w = t >> 5;
    const int base = b * 4096;

    if (w == 0) { slot[0][lane] = 0ull; slot[1][lane] = 0ull; }
    if (t < 64) ((unsigned long long*)mbox)[t] = 0ull;
    if (t == 0) { srestag[0] = 0u; srestag[1] = 0u; }

    float px[4], py[4], pz[4], dst[4];
#pragma unroll
    for (int j = 0; j < 4; j++) {
        float4 p = g_xyz[base + j * 1024 + t];
        sxyz[j * 1024 + t] = p;
        px[j] = p.x; py[j] = p.y; pz[j] = p.z; dst[j] = 1e10f;
    }
    float4 c0 = g_xyz[0];
    float ccx = c0.x, ccy = c0.y, ccz = c0.z;
    __syncthreads();
    asm volatile("barrier.cluster.arrive.aligned;" ::: "memory");
    asm volatile("barrier.cluster.wait.aligned;" ::: "memory");

    for (int i = 0; i < NP1; i++) {
        if (b == 0 && t == 0)
            g_newxyz1[i] = make_float4(ccx, ccy, ccz, 0.f);
        if (i == NP1 - 1) break;
        const unsigned tag = (unsigned)(i + 1);
        const int par = i & 1;

        float bv = -1.f; int bi = 0x7fffffff;
#pragma unroll
        for (int j = 0; j < 4; j++) {
            float d = sqdist(px[j], py[j], pz[j], ccx, ccy, ccz);
            dst[j] = fminf(dst[j], d);
            if (dst[j] > bv) { bv = dst[j]; bi = base + j * 1024 + t; }
        }
        unsigned wmax, widx;
        warp_argmax(__float_as_uint(bv), (unsigned)bi, wmax, widx);

        if (w != 0) {
            if (lane == 0)
                slot[par][w] = ((unsigned long long)wmax << 32)
                             | ((unsigned long long)(widx & 0x7fffu) << 16)
                             | (unsigned long long)tag;
            while (srestag[par] != tag) { }
            ccx = sresx[par]; ccy = sresy[par]; ccz = sresz[par];
        } else {
            // gather 32 warp partials (lane L <- slot L; lane 0 holds its own)
            unsigned vb, ib; bool done;
            if (lane == 0) { vb = wmax; ib = widx; done = true; }
            else           { vb = 0u;   ib = 0xffffffffu; done = false; }
            while (!__all_sync(0xffffffffu, done)) {
                if (!done) {
                    unsigned long long s = slot[par][lane];
                    if ((unsigned)(s & 0xffffull) == tag) {
                        vb = (unsigned)(s >> 32);
                        ib = (unsigned)((s >> 16) & 0x7fffull);
                        done = true;
                    }
                }
            }
            unsigned bmax, bidx;
            warp_argmax(vb, ib, bmax, bidx);

            float cx = 0.f, cy = 0.f, cz = 0.f;
            if (lane == 0) {
                float4 wn = sxyz[bidx - base];
                cx = wn.x; cy = wn.y; cz = wn.z;
            }
            cx = __shfl_sync(0xffffffffu, cx, 0);
            cy = __shfl_sync(0xffffffffu, cy, 0);
            cz = __shfl_sync(0xffffffffu, cz, 0);

            // DSMEM broadcast: lane L pushes this CTA's packet to peer L's mailbox
            if (lane < 8) {
                uint32_t laddr = smem_u32(&mbox[par][b][0]);
                uint32_t raddr = mapa_cluster(laddr, (uint32_t)lane);
                st_cluster_u64(raddr,
                    ((unsigned long long)__float_as_uint(cx) << 32) | tag);
                st_cluster_u64(raddr + 8,
                    ((unsigned long long)__float_as_uint(cy) << 32) | tag);
                st_cluster_u64(raddr + 16,
                    ((unsigned long long)__float_as_uint(cz) << 32) | tag);
                st_cluster_u64(raddr + 24,
                    ((unsigned long long)bmax << 32)
                    | ((unsigned long long)(bidx & 0x7fffu) << 16) | tag);
            }

            // poll own mailbox rows (lane L <- src CTA L), all 4 words tagged
            bool d2 = (lane >= 8);
            unsigned v2 = 0u, id2 = 0xffffffffu;
            float cxr = 0.f, cyr = 0.f, czr = 0.f;
            uint32_t rowaddr = smem_u32(&mbox[par][lane & 7][0]);
            while (!__all_sync(0xffffffffu, d2)) {
                if (!d2) {
                    unsigned long long A = ldv_sh_u64(rowaddr);
                    unsigned long long B = ldv_sh_u64(rowaddr + 8);
                    unsigned long long C = ldv_sh_u64(rowaddr + 16);
                    unsigned long long D = ldv_sh_u64(rowaddr + 24);
                    if ((unsigned)(A & 0xffffull) == tag &&
                        (unsigned)(B & 0xffffull) == tag &&
                        (unsigned)(C & 0xffffull) == tag &&
                        (unsigned)(D & 0xffffull) == tag) {
                        cxr = __uint_as_float((unsigned)(A >> 32));
                        cyr = __uint_as_float((unsigned)(B >> 32));
                        czr = __uint_as_float((unsigned)(C >> 32));
                        v2  = (unsigned)(D >> 32);
                        id2 = (unsigned)((D >> 16) & 0x7fffull);
                        d2 = true;
                    }
                }
            }
            unsigned gmax, gidx;
            warp_argmax(v2, id2, gmax, gidx);
            int wl = (int)(gidx >> 12);           // 4096 pts per CTA -> src lane
            float nx = __shfl_sync(0xffffffffu, cxr, wl);
            float ny = __shfl_sync(0xffffffffu, cyr, wl);
            float nz = __shfl_sync(0xffffffffu, czr, wl);
            if (lane == 0) {
                sresx[par] = nx; sresy[par] = ny; sresz[par] = nz;
                asm volatile("membar.cta;" ::: "memory");
                srestag[par] = tag;
            }
            ccx = nx; ccy = ny; ccz = nz;
        }
    }
    asm volatile("barrier.cluster.arrive.aligned;" ::: "memory");
    asm volatile("barrier.cluster.wait.aligned;" ::: "memory");
}

// ---------------- FPS2: single block, REDUX argmax, writes newxyz2 directly -----
__global__ void __launch_bounds__(512) fps2_kernel() {
    __shared__ float4 sx[NP1];
    __shared__ float  sval[2][16];
    __shared__ int    sidx[2][16];
    const int t = threadIdx.x, lane = t & 31, wp = t >> 5;
    for (int i = t; i < NP1; i += 512) sx[i] = g_newxyz1[i];
    __syncthreads();
    float px[4], py[4], pz[4], dst[4];
#pragma unroll
    for (int j = 0; j < 4; j++) {
        float4 p = sx[j * 512 + t];
        px[j] = p.x; py[j] = p.y; pz[j] = p.z; dst[j] = 1e10f;
    }
    int cur = 0;
    for (int i = 0; i < NP2; i++) {
        if (t == 0) {
            float4 c = sx[cur];
            g_newxyz2[i] = make_float4(c.x, c.y, c.z, 0.f);
        }
        if (i == NP2 - 1) break;
        float4 c = sx[cur];
        float bv = -1.f; int bi = 0x7fffffff;
#pragma unroll
        for (int j = 0; j < 4; j++) {
            float d = sqdist(px[j], py[j], pz[j], c.x, c.y, c.z);
            dst[j] = fminf(dst[j], d);
            if (dst[j] > bv) { bv = dst[j]; bi = j * 512 + t; }
        }
        unsigned wmax, widx;
        warp_argmax(__float_as_uint(bv), (unsigned)bi, wmax, widx);
        int par = i & 1;
        if (lane == 0) { sval[par][wp] = __uint_as_float(wmax); sidx[par][wp] = (int)widx; }
        __syncthreads();
        unsigned vb = (lane < 16) ? __float_as_uint(sval[par][lane]) : 0u;
        unsigned ib = (lane < 16) ? (unsigned)sidx[par][lane] : 0xffffffffu;
        unsigned bmax, bidx;
        warp_argmax(vb, ib, bmax, bidx);
        cur = (int)bidx;
    }
}

// ------ ball query: warp/center, 4x-unrolled MLP scan, ascending == top_k smallest
__global__ void ballquery_kernel(const float4* __restrict__ pts, int n,
                                 const float4* __restrict__ centers, int rows,
                                 float r2, int nsample, int* __restrict__ gidx) {
    int gw = (blockIdx.x * blockDim.x + threadIdx.x) >> 5;
    int lane = threadIdx.x & 31;
    if (gw >= rows) return;
    float4 c = centers[gw];
    int found = 0, first = 0;
    int* out = &gidx[(size_t)gw * nsample];
    for (int base = 0; base < n; base += 128) {
        float4 p0 = pts[base + lane];
        float4 p1 = pts[base + 32 + lane];
        float4 p2 = pts[base + 64 + lane];
        float4 p3 = pts[base + 96 + lane];
        bool in0 = sqdist(p0.x, p0.y, p0.z, c.x, c.y, c.z) <= r2;
        bool in1 = sqdist(p1.x, p1.y, p1.z, c.x, c.y, c.z) <= r2;
        bool in2 = sqdist(p2.x, p2.y, p2.z, c.x, c.y, c.z) <= r2;
        bool in3 = sqdist(p3.x, p3.y, p3.z, c.x, c.y, c.z) <= r2;
        unsigned m0 = __ballot_sync(0xffffffffu, in0);
        unsigned m1 = __ballot_sync(0xffffffffu, in1);
        unsigned m2 = __ballot_sync(0xffffffffu, in2);
        unsigned m3 = __ballot_sync(0xffffffffu, in3);
        unsigned mm[4] = {m0, m1, m2, m3};
        bool     ii[4] = {in0, in1, in2, in3};
#pragma unroll
        for (int s = 0; s < 4; s++) {
            unsigned m = mm[s];
            if (found == 0 && m) first = base + s * 32 + __ffs(m) - 1;
            int pos = found + __popc(m & ((1u << lane) - 1u));
            if (ii[s] && pos < nsample) out[pos] = base + s * 32 + lane;
            found += __popc(m);
        }
        if (found >= nsample) break;
    }
    for (int p = found + lane; p < nsample; p += 32) out[p] = first;
}

// ---------------- grouping ----------------
__global__ void group1_kernel() {
    int m = blockIdx.x * blockDim.x + threadIdx.x;   // < 65536
    int s = m >> 5;
    int g = g_gidx1[m];
    float4 p = g_xyz[g], c = g_newxyz1[s];
    float* o = &g_h0[(size_t)m * 16];
    o[0] = __fsub_rn(p.x, c.x); o[1] = __fsub_rn(p.y, c.y); o[2] = __fsub_rn(p.z, c.z);
    const float* f = &g_feats[(size_t)g * 12];
#pragma unroll
    for (int j = 0; j < 12; j++) o[3 + j] = f[j];
    o[15] = 0.f;
}

__global__ void group2_kernel() {
    int m = blockIdx.x * blockDim.x + threadIdx.x;   // < 32768
    int s = m >> 6;
    int g = g_gidx2[m];
    float4 p = g_newxyz1[g], c = g_newxyz2[s];
    float* o = &g_bufC[(size_t)m * 144];
    o[0] = __fsub_rn(p.x, c.x); o[1] = __fsub_rn(p.y, c.y); o[2] = __fsub_rn(p.z, c.z);
    const float* f = &g_f1[(size_t)g * 128];
#pragma unroll 4
    for (int j = 0; j < 128; j++) o[3 + j] = f[j];
#pragma unroll
    for (int j = 131; j < 144; j++) o[j] = 0.f;
}

__global__ void a3_kernel() {
    int i = blockIdx.x * blockDim.x + threadIdx.x;
    if (i >= NP2 * 272) return;
    int s = i / 272, c = i % 272;
    float v;
    if (c < 3)        { float4 p = g_newxyz2[s]; v = (c == 0) ? p.x : ((c == 1) ? p.y : p.z); }
    else if (c < 259)   v = g_f2[(size_t)s * 256 + (c - 3)];
    else                v = 0.f;
    g_a3[i] = v;
}

// ------------- weight padding: all three layers in one launch -------------------
__global__ void padw_all_kernel(const float* __restrict__ W1, const float* __restrict__ W2,
                                const float* __restrict__ W3) {
    int i = blockIdx.x * blockDim.x + threadIdx.x;
    if (i < 64 * 16) {
        int o = i / 16, k = i % 16;
        g_wp[WP1_OFF + i] = (k < 15) ? W1[(size_t)o * 15 + k] : 0.f;
    } else if (i < 64 * 16 + 128 * 144) {
        int j = i - 64 * 16;
        int o = j / 144, k = j % 144;
        g_wp[WP1_OFF + i] = (k < 131) ? W2[(size_t)o * 131 + k] : 0.f;
    } else if (i < 64 * 16 + 128 * 144 + 256 * 272) {
        int j = i - (64 * 16 + 128 * 144);
        int o = j / 272, k = j % 272;
        g_wp[WP1_OFF + i] = (k < 259) ? W3[(size_t)o * 259 + k] : 0.f;
    }
}

// -------- SGEMM: 128 threads, tile 128x64, 8x8 micro, double-buffered smem.
// C[M,N] = relu(A[M,K] * W[N,K]^T + bias), M%128==0, N%64==0, K%16==0
__global__ void __launch_bounds__(128) gemm_bias_relu(
    const float* __restrict__ A, const float* __restrict__ W,
    const float* __restrict__ bias, float* __restrict__ C,
    int M, int N, int K)
{
    __shared__ float As[2][16][132];
    __shared__ float Bs[2][16][68];
    const int m0 = blockIdx.x * 128;
    const int n0 = blockIdx.y * 64;
    const int tid = threadIdx.x;
    const int tx = tid & 7, ty = tid >> 3;
    const int brow = tid >> 1, bc8 = (tid & 1) << 3;
    float acc[8][8];
#pragma unroll
    for (int i = 0; i < 8; i++)
#pragma unroll
        for (int j = 0; j < 8; j++) acc[i][j] = 0.f;

    const float* Ap = A + (size_t)(m0 + tid) * K;
    const float* Wp = W + (size_t)(n0 + brow) * K + bc8;

    float4 a0 = *reinterpret_cast<const float4*>(Ap);
    float4 a1 = *reinterpret_cast<const float4*>(Ap + 4);
    float4 a2 = *reinterpret_cast<const float4*>(Ap + 8);
    float4 a3 = *reinterpret_cast<const float4*>(Ap + 12);
    float4 w0 = *reinterpret_cast<const float4*>(Wp);
    float4 w1 = *reinterpret_cast<const float4*>(Wp + 4);

    int buf = 0;
    for (int k0 = 0; k0 < K; k0 += 16) {
        As[buf][0][tid]  = a0.x; As[buf][1][tid]  = a0.y; As[buf][2][tid]  = a0.z; As[buf][3][tid]  = a0.w;
        As[buf][4][tid]  = a1.x; As[buf][5][tid]  = a1.y; As[buf][6][tid]  = a1.z; As[buf][7][tid]  = a1.w;
        As[buf][8][tid]  = a2.x; As[buf][9][tid]  = a2.y; As[buf][10][tid] = a2.z; As[buf][11][tid] = a2.w;
        As[buf][12][tid] = a3.x; As[buf][13][tid] = a3.y; As[buf][14][tid] = a3.z; As[buf][15][tid] = a3.w;
        Bs[buf][bc8 + 0][brow] = w0.x; Bs[buf][bc8 + 1][brow] = w0.y;
        Bs[buf][bc8 + 2][brow] = w0.z; Bs[buf][bc8 + 3][brow] = w0.w;
        Bs[buf][bc8 + 4][brow] = w1.x; Bs[buf][bc8 + 5][brow] = w1.y;
        Bs[buf][bc8 + 6][brow] = w1.z; Bs[buf][bc8 + 7][brow] = w1.w;
        __syncthreads();

        if (k0 + 16 < K) {
            a0 = *reinterpret_cast<const float4*>(Ap + k0 + 16);
            a1 = *reinterpret_cast<const float4*>(Ap + k0 + 20);
            a2 = *reinterpret_cast<const float4*>(Ap + k0 + 24);
            a3 = *reinterpret_cast<const float4*>(Ap + k0 + 28);
            w0 = *reinterpret_cast<const float4*>(Wp + k0 + 16);
            w1 = *reinterpret_cast<const float4*>(Wp + k0 + 20);
        }
#pragma unroll
        for (int k = 0; k < 16; k++) {
            float a[8], b[8];
            *reinterpret_cast<float4*>(&a[0]) = *reinterpret_cast<const float4*>(&As[buf][k][ty * 8]);
            *reinterpret_cast<float4*>(&a[4]) = *reinterpret_cast<const float4*>(&As[buf][k][ty * 8 + 4]);
            *reinterpret_cast<float4*>(&b[0]) = *reinterpret_cast<const float4*>(&Bs[buf][k][tx * 8]);
            *reinterpret_cast<float4*>(&b[4]) = *reinterpret_cast<const float4*>(&Bs[buf][k][tx * 8 + 4]);
#pragma unroll
            for (int i = 0; i < 8; i++)
#pragma unroll
                for (int j = 0; j < 8; j++)
                    acc[i][j] += a[i] * b[j];
        }
        buf ^= 1;
    }
    float4 bv0 = *reinterpret_cast<const float4*>(bias + n0 + tx * 8);
    float4 bv1 = *reinterpret_cast<const float4*>(bias + n0 + tx * 8 + 4);
#pragma unroll
    for (int i = 0; i < 8; i++) {
        float4 o0, o1;
        o0.x = fmaxf(acc[i][0] + bv0.x, 0.f);
        o0.y = fmaxf(acc[i][1] + bv0.y, 0.f);
        o0.z = fmaxf(acc[i][2] + bv0.z, 0.f);
        o0.w = fmaxf(acc[i][3] + bv0.w, 0.f);
        o1.x = fmaxf(acc[i][4] + bv1.x, 0.f);
        o1.y = fmaxf(acc[i][5] + bv1.y, 0.f);
        o1.z = fmaxf(acc[i][6] + bv1.z, 0.f);
        o1.w = fmaxf(acc[i][7] + bv1.w, 0.f);
        float* crow = C + (size_t)(m0 + ty * 8 + i) * N + n0 + tx * 8;
        *reinterpret_cast<float4*>(crow)     = o0;
        *reinterpret_cast<float4*>(crow + 4) = o1;
    }
}

// ---------------- max pools ----------------
__global__ void maxpool1_kernel() {
    int i = blockIdx.x * blockDim.x + threadIdx.x;   // < 2048*128
    int s = i >> 7, c = i & 127;
    const float* base = &g_bufC[(size_t)s * 32 * 128 + c];
    float v = base[0];
#pragma unroll
    for (int k = 1; k < 32; k++) v = fmaxf(v, base[(size_t)k * 128]);
    g_f1[i] = v;
}
__global__ void maxpool2_kernel() {
    int i = blockIdx.x * blockDim.x + threadIdx.x;   // < 512*256
    int s = i >> 8, c = i & 255;
    const float* base = &g_bufD[(size_t)s * 64 * 256 + c];
    float v = base[0];
#pragma unroll
    for (int k = 1; k < 64; k++) v = fmaxf(v, base[(size_t)k * 256]);
    g_f2[i] = v;
}
__global__ void finalmax_kernel(float* __restrict__ out) {
    int c = blockIdx.x * blockDim.x + threadIdx.x;
    if (c >= 1024) return;
    float v = g_bufC[c];
    for (int s = 1; s < 512; s++) v = fmaxf(v, g_bufC[(size_t)s * 1024 + c]);
    out[c] = v;
}

// ---------------- launch ----------------
extern "C" void kernel_launch(void* const* d_in, const int* in_sizes, int n_in,
                              void* d_out, int out_size) {
    const float* points = (const float*)d_in[0];
    const float* prop   = (const float*)d_in[1];

    // Input binding: runtime-detect tensor ordering (dict-interleaved vs signature).
    const float *w10, *w11, *w12, *b10, *b11, *b12;
    const float *w20, *w21, *w22, *b20, *b21, *b22;
    const float *w30, *w31, *w32, *b30, *b31, *b32;
    if (in_sizes[3] == 64) {
        w10 = (const float*)d_in[2];  b10 = (const float*)d_in[3];
        w11 = (const float*)d_in[4];  b11 = (const float*)d_in[5];
        w12 = (const float*)d_in[6];  b12 = (const float*)d_in[7];
        w20 = (const float*)d_in[8];  b20 = (const float*)d_in[9];
        w21 = (const float*)d_in[10]; b21 = (const float*)d_in[11];
        w22 = (const float*)d_in[12]; b22 = (const float*)d_in[13];
        w30 = (const float*)d_in[14]; b30 = (const float*)d_in[15];
        w31 = (const float*)d_in[16]; b31 = (const float*)d_in[17];
        w32 = (const float*)d_in[18]; b32 = (const float*)d_in[19];
    } else {
        w10 = (const float*)d_in[2];  w11 = (const float*)d_in[3];  w12 = (const float*)d_in[4];
        b10 = (const float*)d_in[5];  b11 = (const float*)d_in[6];  b12 = (const float*)d_in[7];
        w20 = (const float*)d_in[8];  w21 = (const float*)d_in[9];  w22 = (const float*)d_in[10];
        b20 = (const float*)d_in[11]; b21 = (const float*)d_in[12]; b22 = (const float*)d_in[13];
        w30 = (const float*)d_in[14]; w31 = (const float*)d_in[15]; w32 = (const float*)d_in[16];
        b30 = (const float*)d_in[17]; b31 = (const float*)d_in[18]; b32 = (const float*)d_in[19];
    }
    float* out = (float*)d_out;

    float *h0, *bufA, *bufB, *bufC, *bufD, *wp, *a3;
    float4 *xyz, *nx1, *nx2;
    int *gidx1, *gidx2;
    cudaGetSymbolAddress((void**)&h0,    g_h0);
    cudaGetSymbolAddress((void**)&bufA,  g_bufA);
    cudaGetSymbolAddress((void**)&bufB,  g_bufB);
    cudaGetSymbolAddress((void**)&bufC,  g_bufC);
    cudaGetSymbolAddress((void**)&bufD,  g_bufD);
    cudaGetSymbolAddress((void**)&wp,    g_wp);
    cudaGetSymbolAddress((void**)&a3,    g_a3);
    cudaGetSymbolAddress((void**)&xyz,   g_xyz);
    cudaGetSymbolAddress((void**)&nx1,   g_newxyz1);
    cudaGetSymbolAddress((void**)&nx2,   g_newxyz2);
    cudaGetSymbolAddress((void**)&gidx1, g_gidx1);
    cudaGetSymbolAddress((void**)&gidx2, g_gidx2);

    cudaFuncSetAttribute(fps1_kernel,
                         cudaFuncAttributeMaxDynamicSharedMemorySize, 65536);

    const float r2_1 = (float)(0.4 * 0.4);
    const float r2_2 = (float)(0.8 * 0.8);

    prep_kernel<<<N0 / 256, 256>>>(points, prop);
    padw_all_kernel<<<(64*16 + 128*144 + 256*272 + 255) / 256, 256>>>(w10, w20, w30);

    // SA1 (fps1 writes g_newxyz1 directly; 8-CTA cluster, 64KB dynamic smem)
    fps1_kernel<<<8, 1024, 65536>>>();
    ballquery_kernel<<<(NP1 * 32 + 255) / 256, 256>>>(xyz, N0, nx1, NP1, r2_1, NS1, gidx1);
    group1_kernel<<<(NP1 * NS1 + 255) / 256, 256>>>();
    {
        dim3 g1(65536 / 128, 1);  gemm_bias_relu<<<g1, 128>>>(h0,   wp + WP1_OFF, b10, bufA, 65536, 64, 16);
        dim3 g2(65536 / 128, 1);  gemm_bias_relu<<<g2, 128>>>(bufA, w11,          b11, bufB, 65536, 64, 64);
        dim3 g3(65536 / 128, 2);  gemm_bias_relu<<<g3, 128>>>(bufB, w12,          b12, bufC, 65536, 128, 64);
    }
    maxpool1_kernel<<<(NP1 * 128 + 255) / 256, 256>>>();

    // SA2 (fps2 writes g_newxyz2 directly)
    fps2_kernel<<<1, 512>>>();
    ballquery_kernel<<<(NP2 * 32 + 255) / 256, 256>>>(nx1, NP1, nx2, NP2, r2_2, NS2, gidx2);
    group2_kernel<<<(NP2 * NS2 + 255) / 256, 256>>>();
    {
        dim3 g4(32768 / 128, 2);  gemm_bias_relu<<<g4, 128>>>(bufC, wp + WP2_OFF, b20, bufA, 32768, 128, 144);
        dim3 g5(32768 / 128, 2);  gemm_bias_relu<<<g5, 128>>>(bufA, w21,          b21, bufB, 32768, 128, 128);
        dim3 g6(32768 / 128, 4);  gemm_bias_relu<<<g6, 128>>>(bufB, w22,          b22, bufD, 32768, 256, 128);
    }
    maxpool2_kernel<<<(NP2 * 256 + 255) / 256, 256>>>();

    // SA3
    a3_kernel<<<(NP2 * 272 + 255) / 256, 256>>>();
    {
        dim3 g7(512 / 128, 4);    gemm_bias_relu<<<g7, 128>>>(a3,   wp + WP3_OFF, b30, bufA, 512, 256, 272);
        dim3 g8(512 / 128, 8);    gemm_bias_relu<<<g8, 128>>>(bufA, w31,          b31, bufB, 512, 512, 256);
        dim3 g9(512 / 128, 16);   gemm_bias_relu<<<g9, 128>>>(bufB, w32,          b32, bufC, 512, 1024, 512);
    }
    finalmax_kernel<<<4, 256>>>(out);
}

// round 11
// speedup vs baseline: 1.1288x; 1.1288x over previous
#include <cuda_runtime.h>
#include <stdint.h>
#include <stddef.h>

#define N0   32768
#define NP1  2048
#define NS1  32
#define NP2  512
#define NS2  64

// ---------------- static scratch (no runtime allocation allowed) ----------------
__device__ float4 g_xyz[N0];
__device__ float  g_feats[N0 * 12];
__device__ float4 g_newxyz1[NP1];
__device__ int    g_gidx1[NP1 * NS1];
__device__ float  g_h0[NP1 * NS1 * 16];            // SA1 L0 input, K 15->16
__device__ float  g_bufA[65536 * 64];              // 16 MB
__device__ float  g_bufB[65536 * 64];              // 16 MB
__device__ float  g_bufC[65536 * 128];             // 32 MB
__device__ float  g_bufD[32768 * 256];             // 32 MB
__device__ float  g_f1[NP1 * 128];
__device__ float4 g_newxyz2[NP2];
__device__ int    g_gidx2[NP2 * NS2];
__device__ float  g_f2[NP2 * 256];
__device__ float  g_a3[NP2 * 272];                 // SA3 input, K 259->272
__device__ float  g_wp[64*16 + 128*144 + 256*272]; // padded weights
// FPS1 packets: [parity][block] -> 128-byte slot (uint4[8]);
// chunk0 = (tag,val,idx,_), chunk1 = (tag,cx,cy,cz). Dual-tag: reader accepts
// only when BOTH chunks carry the tag -> no write-ordering fence needed.
__device__ uint4  g_pk2[2][16][8];

#define WP1_OFF 0
#define WP2_OFF (64*16)
#define WP3_OFF (64*16 + 128*144)

// ---------------- helpers ----------------
__device__ __forceinline__ uint4 ldv4(const uint4* p) {
    uint4 v;
    asm volatile("ld.volatile.global.v4.u32 {%0,%1,%2,%3}, [%4];"
                 : "=r"(v.x), "=r"(v.y), "=r"(v.z), "=r"(v.w) : "l"(p));
    return v;
}
__device__ __forceinline__ void stv4(uint4* p, uint4 v) {
    asm volatile("st.volatile.global.v4.u32 [%0], {%1,%2,%3,%4};"
                 :: "l"(p), "r"(v.x), "r"(v.y), "r"(v.z), "r"(v.w) : "memory");
}
// square-then-add (no FMA) to mirror XLA's elementwise (x-c)**2 then reduce
__device__ __forceinline__ float sqdist(float px, float py, float pz,
                                        float cx, float cy, float cz) {
    float dx = __fsub_rn(px, cx), dy = __fsub_rn(py, cy), dz = __fsub_rn(pz, cz);
    return __fadd_rn(__fadd_rn(__fmul_rn(dx, dx), __fmul_rn(dy, dy)), __fmul_rn(dz, dz));
}
// warp argmax over non-negative floats (bits order-isomorphic), tie -> min index.
__device__ __forceinline__ void warp_argmax(unsigned vbits, unsigned idx,
                                            unsigned& maxbits, unsigned& minidx) {
    maxbits = __reduce_max_sync(0xffffffffu, vbits);
    minidx  = __reduce_min_sync(0xffffffffu, (vbits == maxbits) ? idx : 0xffffffffu);
}

// ---------------- stage 0: xyz + feats (+ zero FPS1 packets for replay) ---------
__global__ void prep_kernel(const float* __restrict__ pts, const float* __restrict__ prop) {
    int i = blockIdx.x * blockDim.x + threadIdx.x;
    if (blockIdx.x == 0 && threadIdx.x < 256)
        ((uint4*)g_pk2)[threadIdx.x] = make_uint4(0u, 0u, 0u, 0u);
    if (i >= N0) return;
    float x = prop[0], y = prop[1], w = prop[3];
    float hw = __fmul_rn(w, 0.5f);
    float px = pts[i * 3 + 0], py = pts[i * 3 + 1], pz = pts[i * 3 + 2];
    float ax = __fsub_rn(px, x), ay = __fsub_rn(py, y);
    g_xyz[i] = make_float4(ax, ay, pz, 0.f);
    float oxp = __fadd_rn(x, hw), oxm = __fsub_rn(x, hw);
    float oyp = __fadd_rn(y, hw), oym = __fsub_rn(y, hw);
    float* f = &g_feats[(size_t)i * 12];
    f[0] = __fsub_rn(px, oxp); f[1]  = ay;                 f[2]  = pz;
    f[3] = __fsub_rn(px, oxm); f[4]  = ay;                 f[5]  = pz;
    f[6] = ax;                 f[7]  = __fsub_rn(py, oyp); f[8]  = pz;
    f[9] = ax;                 f[10] = __fsub_rn(py, oym); f[11] = pz;
}

// ------ FPS1 (R9 design): 16 blocks, one poller warp, dual-tag packets ----------
__global__ void __launch_bounds__(512) fps1_kernel() {
    __shared__ float4 sxyz[2048];
    __shared__ float  sval[16];
    __shared__ int    sidx[16];
    __shared__ float4 sres[2];             // x,y,z = centroid, w = bitcast(cur)
    const int b = blockIdx.x, t = threadIdx.x;
    const int lane = t & 31, wp = t >> 5;
    const int base = b * 2048;
    float px[4], py[4], pz[4], dst[4];
#pragma unroll
    for (int j = 0; j < 4; j++) {
        float4 p = g_xyz[base + j * 512 + t];
        sxyz[j * 512 + t] = p;
        px[j] = p.x; py[j] = p.y; pz[j] = p.z; dst[j] = 1e10f;
    }
    float4 c0 = g_xyz[0];
    float ccx = c0.x, ccy = c0.y, ccz = c0.z;
    __syncthreads();

    for (int i = 0; i < NP1; i++) {
        if (b == 0 && t == 0)
            g_newxyz1[i] = make_float4(ccx, ccy, ccz, 0.f);
        if (i == NP1 - 1) break;

        float bv = -1.f; int bi = 0x7fffffff;
#pragma unroll
        for (int j = 0; j < 4; j++) {
            float d = sqdist(px[j], py[j], pz[j], ccx, ccy, ccz);
            dst[j] = fminf(dst[j], d);
            if (dst[j] > bv) { bv = dst[j]; bi = base + j * 512 + t; }
        }
        unsigned wmax, widx;
        warp_argmax(__float_as_uint(bv), (unsigned)bi, wmax, widx);
        if (lane == 0) { sval[wp] = __uint_as_float(wmax); sidx[wp] = (int)widx; }
        __syncthreads();

        const int par = i & 1;
        if (wp == 0) {
            const unsigned tag = (unsigned)(i + 1);
            uint4 (*buf)[8] = g_pk2[par];

            unsigned vb = (lane < 16) ? __float_as_uint(sval[lane]) : 0u;
            unsigned ib = (lane < 16) ? (unsigned)sidx[lane] : 0xffffffffu;
            unsigned bmax, bidx;
            warp_argmax(vb, ib, bmax, bidx);
            if (lane == 0) {
                float4 wn = sxyz[bidx - base];
                stv4(&buf[b][1], make_uint4(tag, __float_as_uint(wn.x),
                                            __float_as_uint(wn.y),
                                            __float_as_uint(wn.z)));
                stv4(&buf[b][0], make_uint4(tag, bmax, bidx, 0u));
            }

            bool  done = (lane >= 16);
            unsigned v2b = 0u, id2 = 0xffffffffu;
            float cxr = 0.f, cyr = 0.f, czr = 0.f;
            while (!__all_sync(0xffffffffu, done)) {
                if (!done) {
                    uint4 p = ldv4(&buf[lane][0]);
                    uint4 q = ldv4(&buf[lane][1]);
                    if (p.x == tag && q.x == tag) {
                        v2b = p.y; id2 = p.z;
                        cxr = __uint_as_float(q.y);
                        cyr = __uint_as_float(q.z);
                        czr = __uint_as_float(q.w);
                        done = true;
                    }
                }
            }
            unsigned gmax, gidx;
            warp_argmax(v2b, id2, gmax, gidx);
            int curn = (int)gidx;
            int wb   = curn >> 11;
            float nx = __shfl_sync(0xffffffffu, cxr, wb);
            float ny = __shfl_sync(0xffffffffu, cyr, wb);
            float nz = __shfl_sync(0xffffffffu, czr, wb);
            if (lane == 0) sres[par] = make_float4(nx, ny, nz, 0.f);
        }
        __syncthreads();
        float4 r = sres[par];
        ccx = r.x; ccy = r.y; ccz = r.z;
    }
}

// ------ ball query body: warp/center, 8x-unrolled MLP scan, ascending order -----
__device__ __forceinline__ void ballquery_body(
    const float4* __restrict__ pts, int n, const float4* __restrict__ centers,
    int rows, float r2, int nsample, int* __restrict__ gidx, int gw, int lane)
{
    if (gw >= rows) return;
    float4 c = centers[gw];
    int found = 0, first = 0;
    int* out = &gidx[(size_t)gw * nsample];
    for (int base = 0; base < n; base += 256) {          // n % 256 == 0 for both calls
        float4 p[8];
#pragma unroll
        for (int s = 0; s < 8; s++) p[s] = pts[base + s * 32 + lane];
        unsigned mm[8]; bool ii[8];
#pragma unroll
        for (int s = 0; s < 8; s++) {
            ii[s] = sqdist(p[s].x, p[s].y, p[s].z, c.x, c.y, c.z) <= r2;
            mm[s] = __ballot_sync(0xffffffffu, ii[s]);
        }
#pragma unroll
        for (int s = 0; s < 8; s++) {
            unsigned m = mm[s];
            if (found == 0 && m) first = base + s * 32 + __ffs(m) - 1;
            int pos = found + __popc(m & ((1u << lane) - 1u));
            if (ii[s] && pos < nsample) out[pos] = base + s * 32 + lane;
            found += __popc(m);
        }
        if (found >= nsample) break;
    }
    for (int p2 = found + lane; p2 < nsample; p2 += 32) out[p2] = first;
}

// ------ FPS2 body: 256 threads, 8 pts/thread, REDUX argmax -----------------------
__device__ void fps2_body() {
    __shared__ float4 sx[NP1];
    __shared__ float  sval[2][8];
    __shared__ int    sidx[2][8];
    const int t = threadIdx.x, lane = t & 31, w = t >> 5;
    for (int i = t; i < NP1; i += 256) sx[i] = g_newxyz1[i];
    __syncthreads();
    float px[8], py[8], pz[8], dst[8];
#pragma unroll
    for (int j = 0; j < 8; j++) {
        float4 p = sx[j * 256 + t];
        px[j] = p.x; py[j] = p.y; pz[j] = p.z; dst[j] = 1e10f;
    }
    int cur = 0;
    for (int i = 0; i < NP2; i++) {
        if (t == 0) {
            float4 c = sx[cur];
            g_newxyz2[i] = make_float4(c.x, c.y, c.z, 0.f);
        }
        if (i == NP2 - 1) break;
        float4 c = sx[cur];
        float bv = -1.f; int bi = 0x7fffffff;
#pragma unroll
        for (int j = 0; j < 8; j++) {
            float d = sqdist(px[j], py[j], pz[j], c.x, c.y, c.z);
            dst[j] = fminf(dst[j], d);
            if (dst[j] > bv) { bv = dst[j]; bi = j * 256 + t; }
        }
        unsigned wmax, widx;
        warp_argmax(__float_as_uint(bv), (unsigned)bi, wmax, widx);
        int par = i & 1;
        if (lane == 0) { sval[par][w] = __uint_as_float(wmax); sidx[par][w] = (int)widx; }
        __syncthreads();
        unsigned vb = (lane < 8) ? __float_as_uint(sval[par][lane]) : 0u;
        unsigned ib = (lane < 8) ? (unsigned)sidx[par][lane] : 0xffffffffu;
        unsigned bmax, bidx;
        warp_argmax(vb, ib, bmax, bidx);
        cur = (int)bidx;
    }
}

// ------ fused launch 1: bq1 (blocks 0-255) || fps2 (block 256) -------------------
__global__ void __launch_bounds__(256) bq1_fps2_kernel() {
    if (blockIdx.x < 256) {
        int gw = blockIdx.x * 8 + (threadIdx.x >> 5);
        ballquery_body(g_xyz, N0, g_newxyz1, NP1, (float)(0.4 * 0.4), NS1,
                       g_gidx1, gw, threadIdx.x & 31);
    } else {
        fps2_body();
    }
}

// ------ fused launch 2: group1 (blocks 0-255) || bq2 (blocks 256-319) ------------
__global__ void __launch_bounds__(256) group1_bq2_kernel() {
    if (blockIdx.x < 256) {
        int m = blockIdx.x * 256 + threadIdx.x;      // < 65536
        int s = m >> 5;
        int g = g_gidx1[m];
        float4 p = g_xyz[g], c = g_newxyz1[s];
        float* o = &g_h0[(size_t)m * 16];
        o[0] = __fsub_rn(p.x, c.x); o[1] = __fsub_rn(p.y, c.y); o[2] = __fsub_rn(p.z, c.z);
        const float* f = &g_feats[(size_t)g * 12];
#pragma unroll
        for (int j = 0; j < 12; j++) o[3 + j] = f[j];
        o[15] = 0.f;
    } else {
        int gw = (blockIdx.x - 256) * 8 + (threadIdx.x >> 5);
        ballquery_body(g_newxyz1, NP1, g_newxyz2, NP2, (float)(0.8 * 0.8), NS2,
                       g_gidx2, gw, threadIdx.x & 31);
    }
}

// ---------------- grouping 2 ----------------
__global__ void group2_kernel() {
    int m = blockIdx.x * blockDim.x + threadIdx.x;   // < 32768
    int s = m >> 6;
    int g = g_gidx2[m];
    float4 p = g_newxyz1[g], c = g_newxyz2[s];
    float* o = &g_bufC[(size_t)m * 144];
    o[0] = __fsub_rn(p.x, c.x); o[1] = __fsub_rn(p.y, c.y); o[2] = __fsub_rn(p.z, c.z);
    const float* f = &g_f1[(size_t)g * 128];
#pragma unroll 4
    for (int j = 0; j < 128; j++) o[3 + j] = f[j];
#pragma unroll
    for (int j = 131; j < 144; j++) o[j] = 0.f;
}

__global__ void a3_kernel() {
    int i = blockIdx.x * blockDim.x + threadIdx.x;
    if (i >= NP2 * 272) return;
    int s = i / 272, c = i % 272;
    float v;
    if (c < 3)        { float4 p = g_newxyz2[s]; v = (c == 0) ? p.x : ((c == 1) ? p.y : p.z); }
    else if (c < 259)   v = g_f2[(size_t)s * 256 + (c - 3)];
    else                v = 0.f;
    g_a3[i] = v;
}

// ------------- weight padding: all three layers in one launch -------------------
__global__ void padw_all_kernel(const float* __restrict__ W1, const float* __restrict__ W2,
                                const float* __restrict__ W3) {
    int i = blockIdx.x * blockDim.x + threadIdx.x;
    if (i < 64 * 16) {
        int o = i / 16, k = i % 16;
        g_wp[WP1_OFF + i] = (k < 15) ? W1[(size_t)o * 15 + k] : 0.f;
    } else if (i < 64 * 16 + 128 * 144) {
        int j = i - 64 * 16;
        int o = j / 144, k = j % 144;
        g_wp[WP1_OFF + i] = (k < 131) ? W2[(size_t)o * 131 + k] : 0.f;
    } else if (i < 64 * 16 + 128 * 144 + 256 * 272) {
        int j = i - (64 * 16 + 128 * 144);
        int o = j / 272, k = j % 272;
        g_wp[WP1_OFF + i] = (k < 259) ? W3[(size_t)o * 259 + k] : 0.f;
    }
}

// -------- SGEMM: 128 threads, tile 128x64, 8x8 micro, double-buffered smem.
// C[M,N] = relu(A[M,K] * W[N,K]^T + bias), M%128==0, N%64==0, K%16==0
__global__ void __launch_bounds__(128) gemm_bias_relu(
    const float* __restrict__ A, const float* __restrict__ W,
    const float* __restrict__ bias, float* __restrict__ C,
    int M, int N, int K)
{
    __shared__ float As[2][16][132];
    __shared__ float Bs[2][16][68];
    const int m0 = blockIdx.x * 128;
    const int n0 = blockIdx.y * 64;
    const int tid = threadIdx.x;
    const int tx = tid & 7, ty = tid >> 3;
    const int brow = tid >> 1, bc8 = (tid & 1) << 3;
    float acc[8][8];
#pragma unroll
    for (int i = 0; i < 8; i++)
#pragma unroll
        for (int j = 0; j < 8; j++) acc[i][j] = 0.f;

    const float* Ap = A + (size_t)(m0 + tid) * K;
    const float* Wp = W + (size_t)(n0 + brow) * K + bc8;

    float4 a0 = *reinterpret_cast<const float4*>(Ap);
    float4 a1 = *reinterpret_cast<const float4*>(Ap + 4);
    float4 a2 = *reinterpret_cast<const float4*>(Ap + 8);
    float4 a3 = *reinterpret_cast<const float4*>(Ap + 12);
    float4 w0 = *reinterpret_cast<const float4*>(Wp);
    float4 w1 = *reinterpret_cast<const float4*>(Wp + 4);

    int buf = 0;
    for (int k0 = 0; k0 < K; k0 += 16) {
        As[buf][0][tid]  = a0.x; As[buf][1][tid]  = a0.y; As[buf][2][tid]  = a0.z; As[buf][3][tid]  = a0.w;
        As[buf][4][tid]  = a1.x; As[buf][5][tid]  = a1.y; As[buf][6][tid]  = a1.z; As[buf][7][tid]  = a1.w;
        As[buf][8][tid]  = a2.x; As[buf][9][tid]  = a2.y; As[buf][10][tid] = a2.z; As[buf][11][tid] = a2.w;
        As[buf][12][tid] = a3.x; As[buf][13][tid] = a3.y; As[buf][14][tid] = a3.z; As[buf][15][tid] = a3.w;
        Bs[buf][bc8 + 0][brow] = w0.x; Bs[buf][bc8 + 1][brow] = w0.y;
        Bs[buf][bc8 + 2][brow] = w0.z; Bs[buf][bc8 + 3][brow] = w0.w;
        Bs[buf][bc8 + 4][brow] = w1.x; Bs[buf][bc8 + 5][brow] = w1.y;
        Bs[buf][bc8 + 6][brow] = w1.z; Bs[buf][bc8 + 7][brow] = w1.w;
        __syncthreads();

        if (k0 + 16 < K) {
            a0 = *reinterpret_cast<const float4*>(Ap + k0 + 16);
            a1 = *reinterpret_cast<const float4*>(Ap + k0 + 20);
            a2 = *reinterpret_cast<const float4*>(Ap + k0 + 24);
            a3 = *reinterpret_cast<const float4*>(Ap + k0 + 28);
            w0 = *reinterpret_cast<const float4*>(Wp + k0 + 16);
            w1 = *reinterpret_cast<const float4*>(Wp + k0 + 20);
        }
#pragma unroll
        for (int k = 0; k < 16; k++) {
            float a[8], b[8];
            *reinterpret_cast<float4*>(&a[0]) = *reinterpret_cast<const float4*>(&As[buf][k][ty * 8]);
            *reinterpret_cast<float4*>(&a[4]) = *reinterpret_cast<const float4*>(&As[buf][k][ty * 8 + 4]);
            *reinterpret_cast<float4*>(&b[0]) = *reinterpret_cast<const float4*>(&Bs[buf][k][tx * 8]);
            *reinterpret_cast<float4*>(&b[4]) = *reinterpret_cast<const float4*>(&Bs[buf][k][tx * 8 + 4]);
#pragma unroll
            for (int i = 0; i < 8; i++)
#pragma unroll
                for (int j = 0; j < 8; j++)
                    acc[i][j] += a[i] * b[j];
        }
        buf ^= 1;
    }
    float4 bv0 = *reinterpret_cast<const float4*>(bias + n0 + tx * 8);
    float4 bv1 = *reinterpret_cast<const float4*>(bias + n0 + tx * 8 + 4);
#pragma unroll
    for (int i = 0; i < 8; i++) {
        float4 o0, o1;
        o0.x = fmaxf(acc[i][0] + bv0.x, 0.f);
        o0.y = fmaxf(acc[i][1] + bv0.y, 0.f);
        o0.z = fmaxf(acc[i][2] + bv0.z, 0.f);
        o0.w = fmaxf(acc[i][3] + bv0.w, 0.f);
        o1.x = fmaxf(acc[i][4] + bv1.x, 0.f);
        o1.y = fmaxf(acc[i][5] + bv1.y, 0.f);
        o1.z = fmaxf(acc[i][6] + bv1.z, 0.f);
        o1.w = fmaxf(acc[i][7] + bv1.w, 0.f);
        float* crow = C + (size_t)(m0 + ty * 8 + i) * N + n0 + tx * 8;
        *reinterpret_cast<float4*>(crow)     = o0;
        *reinterpret_cast<float4*>(crow + 4) = o1;
    }
}

// ---------------- max pools ----------------
__global__ void maxpool1_kernel() {
    int i = blockIdx.x * blockDim.x + threadIdx.x;   // < 2048*128
    int s = i >> 7, c = i & 127;
    const float* base = &g_bufC[(size_t)s * 32 * 128 + c];
    float v = base[0];
#pragma unroll
    for (int k = 1; k < 32; k++) v = fmaxf(v, base[(size_t)k * 128]);
    g_f1[i] = v;
}
__global__ void maxpool2_kernel() {
    int i = blockIdx.x * blockDim.x + threadIdx.x;   // < 512*256
    int s = i >> 8, c = i & 255;
    const float* base = &g_bufD[(size_t)s * 64 * 256 + c];
    float v = base[0];
#pragma unroll
    for (int k = 1; k < 64; k++) v = fmaxf(v, base[(size_t)k * 256]);
    g_f2[i] = v;
}
__global__ void finalmax_kernel(float* __restrict__ out) {
    int c = blockIdx.x * blockDim.x + threadIdx.x;
    if (c >= 1024) return;
    float v = g_bufC[c];
    for (int s = 1; s < 512; s++) v = fmaxf(v, g_bufC[(size_t)s * 1024 + c]);
    out[c] = v;
}

// ---------------- launch ----------------
extern "C" void kernel_launch(void* const* d_in, const int* in_sizes, int n_in,
                              void* d_out, int out_size) {
    const float* points = (const float*)d_in[0];
    const float* prop   = (const float*)d_in[1];

    // Input binding: runtime-detect tensor ordering (dict-interleaved vs signature).
    const float *w10, *w11, *w12, *b10, *b11, *b12;
    const float *w20, *w21, *w22, *b20, *b21, *b22;
    const float *w30, *w31, *w32, *b30, *b31, *b32;
    if (in_sizes[3] == 64) {
        w10 = (const float*)d_in[2];  b10 = (const float*)d_in[3];
        w11 = (const float*)d_in[4];  b11 = (const float*)d_in[5];
        w12 = (const float*)d_in[6];  b12 = (const float*)d_in[7];
        w20 = (const float*)d_in[8];  b20 = (const float*)d_in[9];
        w21 = (const float*)d_in[10]; b21 = (const float*)d_in[11];
        w22 = (const float*)d_in[12]; b22 = (const float*)d_in[13];
        w30 = (const float*)d_in[14]; b30 = (const float*)d_in[15];
        w31 = (const float*)d_in[16]; b31 = (const float*)d_in[17];
        w32 = (const float*)d_in[18]; b32 = (const float*)d_in[19];
    } else {
        w10 = (const float*)d_in[2];  w11 = (const float*)d_in[3];  w12 = (const float*)d_in[4];
        b10 = (const float*)d_in[5];  b11 = (const float*)d_in[6];  b12 = (const float*)d_in[7];
        w20 = (const float*)d_in[8];  w21 = (const float*)d_in[9];  w22 = (const float*)d_in[10];
        b20 = (const float*)d_in[11]; b21 = (const float*)d_in[12]; b22 = (const float*)d_in[13];
        w30 = (const float*)d_in[14]; w31 = (const float*)d_in[15]; w32 = (const float*)d_in[16];
        b30 = (const float*)d_in[17]; b31 = (const float*)d_in[18]; b32 = (const float*)d_in[19];
    }
    float* out = (float*)d_out;

    float *h0, *bufA, *bufB, *bufC, *bufD, *wp, *a3;
    cudaGetSymbolAddress((void**)&h0,    g_h0);
    cudaGetSymbolAddress((void**)&bufA,  g_bufA);
    cudaGetSymbolAddress((void**)&bufB,  g_bufB);
    cudaGetSymbolAddress((void**)&bufC,  g_bufC);
    cudaGetSymbolAddress((void**)&bufD,  g_bufD);
    cudaGetSymbolAddress((void**)&wp,    g_wp);
    cudaGetSymbolAddress((void**)&a3,    g_a3);

    // stage 0 (also zeroes FPS1 packets -> replay-safe)
    prep_kernel<<<N0 / 256, 256>>>(points, prop);
    padw_all_kernel<<<(64*16 + 128*144 + 256*272 + 255) / 256, 256>>>(w10, w20, w30);

    // SA1 (fps1 writes g_newxyz1 directly)
    fps1_kernel<<<16, 512>>>();
    bq1_fps2_kernel<<<257, 256>>>();                 // bq1 || fps2
    group1_bq2_kernel<<<320, 256>>>();               // group1 || bq2
    {
        dim3 g1(65536 / 128, 1);  gemm_bias_relu<<<g1, 128>>>(h0,   wp + WP1_OFF, b10, bufA, 65536, 64, 16);
        dim3 g2(65536 / 128, 1);  gemm_bias_relu<<<g2, 128>>>(bufA, w11,          b11, bufB, 65536, 64, 64);
        dim3 g3(65536 / 128, 2);  gemm_bias_relu<<<g3, 128>>>(bufB, w12,          b12, bufC, 65536, 128, 64);
    }
    maxpool1_kernel<<<(NP1 * 128 + 255) / 256, 256>>>();

    // SA2
    group2_kernel<<<(NP2 * NS2 + 255) / 256, 256>>>();
    {
        dim3 g4(32768 / 128, 2);  gemm_bias_relu<<<g4, 128>>>(bufC, wp + WP2_OFF, b20, bufA, 32768, 128, 144);
        dim3 g5(32768 / 128, 2);  gemm_bias_relu<<<g5, 128>>>(bufA, w21,          b21, bufB, 32768, 128, 128);
        dim3 g6(32768 / 128, 4);  gemm_bias_relu<<<g6, 128>>>(bufB, w22,          b22, bufD, 32768, 256, 128);
    }
    maxpool2_kernel<<<(NP2 * 256 + 255) / 256, 256>>>();

    // SA3
    a3_kernel<<<(NP2 * 272 + 255) / 256, 256>>>();
    {
        dim3 g7(512 / 128, 4);    gemm_bias_relu<<<g7, 128>>>(a3,   wp + WP3_OFF, b30, bufA, 512, 256, 272);
        dim3 g8(512 / 128, 8);    gemm_bias_relu<<<g8, 128>>>(bufA, w31,          b31, bufB, 512, 512, 256);
        dim3 g9(512 / 128, 16);   gemm_bias_relu<<<g9, 128>>>(bufB, w32,          b32, bufC, 512, 1024, 512);
    }
    finalmax_kernel<<<4, 256>>>(out);
}

// round 12
// speedup vs baseline: 1.1966x; 1.0601x over previous
#include <cuda_runtime.h>
#include <stdint.h>
#include <stddef.h>

#define N0   32768
#define NP1  2048
#define NS1  32
#define NP2  512
#define NS2  64

// ---------------- static scratch (no runtime allocation allowed) ----------------
__device__ float4 g_xyz[N0];
__device__ float  g_feats[N0 * 12];
__device__ float4 g_newxyz1[NP1];
__device__ int    g_gidx1[NP1 * NS1];
__device__ float  g_h0[NP1 * NS1 * 16];            // SA1 L0 input, K 15->16
__device__ float  g_bufA[65536 * 64];              // 16 MB
__device__ float  g_bufB[65536 * 64];              // 16 MB
__device__ float  g_bufC[65536 * 128];             // 32 MB
__device__ float  g_bufD[32768 * 256];             // 32 MB
__device__ float  g_f1[NP1 * 128];
__device__ float4 g_newxyz2[NP2];
__device__ int    g_gidx2[NP2 * NS2];
__device__ float  g_f2[NP2 * 256];
__device__ float  g_a3[NP2 * 272];                 // SA3 input, K 259->272
__device__ float  g_wp[64*16 + 128*144 + 256*272]; // padded weights
// FPS1 packets: [parity][block] -> 128-byte slot (uint4[8]);
// chunk0 = (tag,val,idx,_), chunk1 = (tag,cx,cy,cz). Dual-tag: reader accepts
// only when BOTH chunks carry the tag -> no write-ordering fence needed.
__device__ uint4  g_pk2[2][16][8];

#define WP1_OFF 0
#define WP2_OFF (64*16)
#define WP3_OFF (64*16 + 128*144)

// ---------------- helpers ----------------
__device__ __forceinline__ uint4 ldv4(const uint4* p) {
    uint4 v;
    asm volatile("ld.volatile.global.v4.u32 {%0,%1,%2,%3}, [%4];"
                 : "=r"(v.x), "=r"(v.y), "=r"(v.z), "=r"(v.w) : "l"(p));
    return v;
}
__device__ __forceinline__ void stv4(uint4* p, uint4 v) {
    asm volatile("st.volatile.global.v4.u32 [%0], {%1,%2,%3,%4};"
                 :: "l"(p), "r"(v.x), "r"(v.y), "r"(v.z), "r"(v.w) : "memory");
}
// square-then-add (no FMA) to mirror XLA's elementwise (x-c)**2 then reduce
__device__ __forceinline__ float sqdist(float px, float py, float pz,
                                        float cx, float cy, float cz) {
    float dx = __fsub_rn(px, cx), dy = __fsub_rn(py, cy), dz = __fsub_rn(pz, cz);
    return __fadd_rn(__fadd_rn(__fmul_rn(dx, dx), __fmul_rn(dy, dy)), __fmul_rn(dz, dz));
}
// warp argmax over non-negative floats (bits order-isomorphic), tie -> min index.
__device__ __forceinline__ void warp_argmax(unsigned vbits, unsigned idx,
                                            unsigned& maxbits, unsigned& minidx) {
    maxbits = __reduce_max_sync(0xffffffffu, vbits);
    minidx  = __reduce_min_sync(0xffffffffu, (vbits == maxbits) ? idx : 0xffffffffu);
}

// ---------------- stage 0: xyz + feats (+ zero FPS1 packets for replay) ---------
__global__ void prep_kernel(const float* __restrict__ pts, const float* __restrict__ prop) {
    int i = blockIdx.x * blockDim.x + threadIdx.x;
    if (blockIdx.x == 0 && threadIdx.x < 256)
        ((uint4*)g_pk2)[threadIdx.x] = make_uint4(0u, 0u, 0u, 0u);
    if (i >= N0) return;
    float x = prop[0], y = prop[1], w = prop[3];
    float hw = __fmul_rn(w, 0.5f);
    float px = pts[i * 3 + 0], py = pts[i * 3 + 1], pz = pts[i * 3 + 2];
    float ax = __fsub_rn(px, x), ay = __fsub_rn(py, y);
    g_xyz[i] = make_float4(ax, ay, pz, 0.f);
    float oxp = __fadd_rn(x, hw), oxm = __fsub_rn(x, hw);
    float oyp = __fadd_rn(y, hw), oym = __fsub_rn(y, hw);
    float* f = &g_feats[(size_t)i * 12];
    f[0] = __fsub_rn(px, oxp); f[1]  = ay;                 f[2]  = pz;
    f[3] = __fsub_rn(px, oxm); f[4]  = ay;                 f[5]  = pz;
    f[6] = ax;                 f[7]  = __fsub_rn(py, oyp); f[8]  = pz;
    f[9] = ax;                 f[10] = __fsub_rn(py, oym); f[11] = pz;
}

// ------ FPS1: 8 blocks x 1024 thr, one poller warp, dual-tag packets ------------
__global__ void __launch_bounds__(1024) fps1_kernel() {
    extern __shared__ float4 sxyz[];       // 4096 pts = 64KB dynamic
    __shared__ float  sval[32];
    __shared__ int    sidx[32];
    __shared__ float4 sres[2];
    const int b = blockIdx.x, t = threadIdx.x;
    const int lane = t & 31, wp = t >> 5;
    const int base = b * 4096;
    float px[4], py[4], pz[4], dst[4];
#pragma unroll
    for (int j = 0; j < 4; j++) {
        float4 p = g_xyz[base + j * 1024 + t];
        sxyz[j * 1024 + t] = p;
        px[j] = p.x; py[j] = p.y; pz[j] = p.z; dst[j] = 1e10f;
    }
    float4 c0 = g_xyz[0];
    float ccx = c0.x, ccy = c0.y, ccz = c0.z;
    __syncthreads();

    for (int i = 0; i < NP1; i++) {
        if (b == 0 && t == 0)
            g_newxyz1[i] = make_float4(ccx, ccy, ccz, 0.f);
        if (i == NP1 - 1) break;

        float bv = -1.f; int bi = 0x7fffffff;
#pragma unroll
        for (int j = 0; j < 4; j++) {
            float d = sqdist(px[j], py[j], pz[j], ccx, ccy, ccz);
            dst[j] = fminf(dst[j], d);
            if (dst[j] > bv) { bv = dst[j]; bi = base + j * 1024 + t; }
        }
        unsigned wmax, widx;
        warp_argmax(__float_as_uint(bv), (unsigned)bi, wmax, widx);
        if (lane == 0) { sval[wp] = __uint_as_float(wmax); sidx[wp] = (int)widx; }
        __syncthreads();

        const int par = i & 1;
        if (wp == 0) {
            const unsigned tag = (unsigned)(i + 1);
            uint4 (*buf)[8] = g_pk2[par];

            // block-level reduce over 32 warp partials (one lane each)
            unsigned vb = __float_as_uint(sval[lane]);
            unsigned ib = (unsigned)sidx[lane];
            unsigned bmax, bidx;
            warp_argmax(vb, ib, bmax, bidx);
            if (lane == 0) {
                float4 wn = sxyz[bidx - base];
                stv4(&buf[b][1], make_uint4(tag, __float_as_uint(wn.x),
                                            __float_as_uint(wn.y),
                                            __float_as_uint(wn.z)));
                stv4(&buf[b][0], make_uint4(tag, bmax, bidx, 0u));
            }

            // poll 8 packets (lane L -> packet L), dual tag accept
            bool  done = (lane >= 8);
            unsigned v2b = 0u, id2 = 0xffffffffu;
            float cxr = 0.f, cyr = 0.f, czr = 0.f;
            while (!__all_sync(0xffffffffu, done)) {
                if (!done) {
                    uint4 p = ldv4(&buf[lane][0]);
                    uint4 q = ldv4(&buf[lane][1]);
                    if (p.x == tag && q.x == tag) {
                        v2b = p.y; id2 = p.z;
                        cxr = __uint_as_float(q.y);
                        cyr = __uint_as_float(q.z);
                        czr = __uint_as_float(q.w);
                        done = true;
                    }
                }
            }
            unsigned gmax, gidx;
            warp_argmax(v2b, id2, gmax, gidx);
            int curn = (int)gidx;
            int wb   = curn >> 12;                 // 4096 pts per block
            float nx = __shfl_sync(0xffffffffu, cxr, wb);
            float ny = __shfl_sync(0xffffffffu, cyr, wb);
            float nz = __shfl_sync(0xffffffffu, czr, wb);
            if (lane == 0) sres[par] = make_float4(nx, ny, nz, 0.f);
        }
        __syncthreads();
        float4 r = sres[par];
        ccx = r.x; ccy = r.y; ccz = r.z;
    }
}

// ------ ball query body (warp/center, 8x MLP scan) — used by bq2 ----------------
__device__ __forceinline__ void ballquery_body(
    const float4* __restrict__ pts, int n, const float4* __restrict__ centers,
    int rows, float r2, int nsample, int* __restrict__ gidx, int gw, int lane)
{
    if (gw >= rows) return;
    float4 c = centers[gw];
    int found = 0, first = 0;
    int* out = &gidx[(size_t)gw * nsample];
    for (int base = 0; base < n; base += 256) {
        float4 p[8];
#pragma unroll
        for (int s = 0; s < 8; s++) p[s] = pts[base + s * 32 + lane];
        unsigned mm[8]; bool ii[8];
#pragma unroll
        for (int s = 0; s < 8; s++) {
            ii[s] = sqdist(p[s].x, p[s].y, p[s].z, c.x, c.y, c.z) <= r2;
            mm[s] = __ballot_sync(0xffffffffu, ii[s]);
        }
#pragma unroll
        for (int s = 0; s < 8; s++) {
            unsigned m = mm[s];
            if (found == 0 && m) first = base + s * 32 + __ffs(m) - 1;
            int pos = found + __popc(m & ((1u << lane) - 1u));
            if (ii[s] && pos < nsample) out[pos] = base + s * 32 + lane;
            found += __popc(m);
        }
        if (found >= nsample) break;
    }
    for (int p2 = found + lane; p2 < nsample; p2 += 32) out[p2] = first;
}

// ------ bq1: block-cooperative smem-staged scan, 8 centers per block -------------
__device__ void bq1_block_body() {
    __shared__ float4 spts[256];
    const int t = threadIdx.x, lane = t & 31, w = t >> 5;
    const int gw = blockIdx.x * 8 + w;               // < 2048 always
    const float r2 = (float)(0.4 * 0.4);
    float4 c = g_newxyz1[gw];
    int found = 0, first = 0;
    int* out = &g_gidx1[(size_t)gw * NS1];
    bool mydone = false;
    for (int base = 0; base < N0; base += 256) {
        spts[t] = g_xyz[base + t];
        __syncthreads();
        if (!mydone) {
#pragma unroll
            for (int s = 0; s < 8; s++) {
                float4 p = spts[s * 32 + lane];
                bool in = sqdist(p.x, p.y, p.z, c.x, c.y, c.z) <= r2;
                unsigned m = __ballot_sync(0xffffffffu, in);
                if (found == 0 && m) first = base + s * 32 + __ffs(m) - 1;
                int pos = found + __popc(m & ((1u << lane) - 1u));
                if (in && pos < NS1) out[pos] = base + s * 32 + lane;
                found += __popc(m);
            }
            if (found >= NS1) mydone = true;
        }
        if (__syncthreads_and(mydone ? 1 : 0)) break;
    }
    for (int p2 = found + lane; p2 < NS1; p2 += 32) out[p2] = first;
}

// ------ FPS2 body: 256 threads, 8 pts/thread, REDUX argmax -----------------------
__device__ void fps2_body() {
    __shared__ float4 sx[NP1];
    __shared__ float  sval[2][8];
    __shared__ int    sidx[2][8];
    const int t = threadIdx.x, lane = t & 31, w = t >> 5;
    for (int i = t; i < NP1; i += 256) sx[i] = g_newxyz1[i];
    __syncthreads();
    float px[8], py[8], pz[8], dst[8];
#pragma unroll
    for (int j = 0; j < 8; j++) {
        float4 p = sx[j * 256 + t];
        px[j] = p.x; py[j] = p.y; pz[j] = p.z; dst[j] = 1e10f;
    }
    int cur = 0;
    for (int i = 0; i < NP2; i++) {
        if (t == 0) {
            float4 c = sx[cur];
            g_newxyz2[i] = make_float4(c.x, c.y, c.z, 0.f);
        }
        if (i == NP2 - 1) break;
        float4 c = sx[cur];
        float bv = -1.f; int bi = 0x7fffffff;
#pragma unroll
        for (int j = 0; j < 8; j++) {
            float d = sqdist(px[j], py[j], pz[j], c.x, c.y, c.z);
            dst[j] = fminf(dst[j], d);
            if (dst[j] > bv) { bv = dst[j]; bi = j * 256 + t; }
        }
        unsigned wmax, widx;
        warp_argmax(__float_as_uint(bv), (unsigned)bi, wmax, widx);
        int par = i & 1;
        if (lane == 0) { sval[par][w] = __uint_as_float(wmax); sidx[par][w] = (int)widx; }
        __syncthreads();
        unsigned vb = (lane < 8) ? __float_as_uint(sval[par][lane]) : 0u;
        unsigned ib = (lane < 8) ? (unsigned)sidx[par][lane] : 0xffffffffu;
        unsigned bmax, bidx;
        warp_argmax(vb, ib, bmax, bidx);
        cur = (int)bidx;
    }
}

// ------ fused launch 1: bq1 (blocks 0-255) || fps2 (block 256) -------------------
__global__ void __launch_bounds__(256) bq1_fps2_kernel() {
    if (blockIdx.x < 256) {
        bq1_block_body();
    } else {
        fps2_body();
    }
}

// ------ fused launch 2: group1 (blocks 0-255) || bq2 (blocks 256-319) ------------
__global__ void __launch_bounds__(256) group1_bq2_kernel() {
    if (blockIdx.x < 256) {
        int m = blockIdx.x * 256 + threadIdx.x;      // < 65536
        int s = m >> 5;
        int g = g_gidx1[m];
        float4 p = g_xyz[g], c = g_newxyz1[s];
        float* o = &g_h0[(size_t)m * 16];
        o[0] = __fsub_rn(p.x, c.x); o[1] = __fsub_rn(p.y, c.y); o[2] = __fsub_rn(p.z, c.z);
        const float* f = &g_feats[(size_t)g * 12];
#pragma unroll
        for (int j = 0; j < 12; j++) o[3 + j] = f[j];
        o[15] = 0.f;
    } else {
        int gw = (blockIdx.x - 256) * 8 + (threadIdx.x >> 5);
        ballquery_body(g_newxyz1, NP1, g_newxyz2, NP2, (float)(0.8 * 0.8), NS2,
                       g_gidx2, gw, threadIdx.x & 31);
    }
}

// ---------------- grouping 2 ----------------
__global__ void group2_kernel() {
    int m = blockIdx.x * blockDim.x + threadIdx.x;   // < 32768
    int s = m >> 6;
    int g = g_gidx2[m];
    float4 p = g_newxyz1[g], c = g_newxyz2[s];
    float* o = &g_bufC[(size_t)m * 144];
    o[0] = __fsub_rn(p.x, c.x); o[1] = __fsub_rn(p.y, c.y); o[2] = __fsub_rn(p.z, c.z);
    const float* f = &g_f1[(size_t)g * 128];
#pragma unroll 4
    for (int j = 0; j < 128; j++) o[3 + j] = f[j];
#pragma unroll
    for (int j = 131; j < 144; j++) o[j] = 0.f;
}

__global__ void a3_kernel() {
    int i = blockIdx.x * blockDim.x + threadIdx.x;
    if (i >= NP2 * 272) return;
    int s = i / 272, c = i % 272;
    float v;
    if (c < 3)        { float4 p = g_newxyz2[s]; v = (c == 0) ? p.x : ((c == 1) ? p.y : p.z); }
    else if (c < 259)   v = g_f2[(size_t)s * 256 + (c - 3)];
    else                v = 0.f;
    g_a3[i] = v;
}

// ------------- weight padding: all three layers in one launch -------------------
__global__ void padw_all_kernel(const float* __restrict__ W1, const float* __restrict__ W2,
                                const float* __restrict__ W3) {
    int i = blockIdx.x * blockDim.x + threadIdx.x;
    if (i < 64 * 16) {
        int o = i / 16, k = i % 16;
        g_wp[WP1_OFF + i] = (k < 15) ? W1[(size_t)o * 15 + k] : 0.f;
    } else if (i < 64 * 16 + 128 * 144) {
        int j = i - 64 * 16;
        int o = j / 144, k = j % 144;
        g_wp[WP1_OFF + i] = (k < 131) ? W2[(size_t)o * 131 + k] : 0.f;
    } else if (i < 64 * 16 + 128 * 144 + 256 * 272) {
        int j = i - (64 * 16 + 128 * 144);
        int o = j / 272, k = j % 272;
        g_wp[WP1_OFF + i] = (k < 259) ? W3[(size_t)o * 259 + k] : 0.f;
    }
}

// -------- SGEMM: 128 threads, tile 128x64, 8x8 micro, double-buffered smem.
// C[M,N] = relu(A[M,K] * W[N,K]^T + bias), M%128==0, N%64==0, K%16==0
__global__ void __launch_bounds__(128) gemm_bias_relu(
    const float* __restrict__ A, const float* __restrict__ W,
    const float* __restrict__ bias, float* __restrict__ C,
    int M, int N, int K)
{
    __shared__ float As[2][16][132];
    __shared__ float Bs[2][16][68];
    const int m0 = blockIdx.x * 128;
    const int n0 = blockIdx.y * 64;
    const int tid = threadIdx.x;
    const int tx = tid & 7, ty = tid >> 3;
    const int brow = tid >> 1, bc8 = (tid & 1) << 3;
    float acc[8][8];
#pragma unroll
    for (int i = 0; i < 8; i++)
#pragma unroll
        for (int j = 0; j < 8; j++) acc[i][j] = 0.f;

    const float* Ap = A + (size_t)(m0 + tid) * K;
    const float* Wp = W + (size_t)(n0 + brow) * K + bc8;

    float4 a0 = *reinterpret_cast<const float4*>(Ap);
    float4 a1 = *reinterpret_cast<const float4*>(Ap + 4);
    float4 a2 = *reinterpret_cast<const float4*>(Ap + 8);
    float4 a3 = *reinterpret_cast<const float4*>(Ap + 12);
    float4 w0 = *reinterpret_cast<const float4*>(Wp);
    float4 w1 = *reinterpret_cast<const float4*>(Wp + 4);

    int buf = 0;
    for (int k0 = 0; k0 < K; k0 += 16) {
        As[buf][0][tid]  = a0.x; As[buf][1][tid]  = a0.y; As[buf][2][tid]  = a0.z; As[buf][3][tid]  = a0.w;
        As[buf][4][tid]  = a1.x; As[buf][5][tid]  = a1.y; As[buf][6][tid]  = a1.z; As[buf][7][tid]  = a1.w;
        As[buf][8][tid]  = a2.x; As[buf][9][tid]  = a2.y; As[buf][10][tid] = a2.z; As[buf][11][tid] = a2.w;
        As[buf][12][tid] = a3.x; As[buf][13][tid] = a3.y; As[buf][14][tid] = a3.z; As[buf][15][tid] = a3.w;
        Bs[buf][bc8 + 0][brow] = w0.x; Bs[buf][bc8 + 1][brow] = w0.y;
        Bs[buf][bc8 + 2][brow] = w0.z; Bs[buf][bc8 + 3][brow] = w0.w;
        Bs[buf][bc8 + 4][brow] = w1.x; Bs[buf][bc8 + 5][brow] = w1.y;
        Bs[buf][bc8 + 6][brow] = w1.z; Bs[buf][bc8 + 7][brow] = w1.w;
        __syncthreads();

        if (k0 + 16 < K) {
            a0 = *reinterpret_cast<const float4*>(Ap + k0 + 16);
            a1 = *reinterpret_cast<const float4*>(Ap + k0 + 20);
            a2 = *reinterpret_cast<const float4*>(Ap + k0 + 24);
            a3 = *reinterpret_cast<const float4*>(Ap + k0 + 28);
            w0 = *reinterpret_cast<const float4*>(Wp + k0 + 16);
            w1 = *reinterpret_cast<const float4*>(Wp + k0 + 20);
        }
#pragma unroll
        for (int k = 0; k < 16; k++) {
            float a[8], b[8];
            *reinterpret_cast<float4*>(&a[0]) = *reinterpret_cast<const float4*>(&As[buf][k][ty * 8]);
            *reinterpret_cast<float4*>(&a[4]) = *reinterpret_cast<const float4*>(&As[buf][k][ty * 8 + 4]);
            *reinterpret_cast<float4*>(&b[0]) = *reinterpret_cast<const float4*>(&Bs[buf][k][tx * 8]);
            *reinterpret_cast<float4*>(&b[4]) = *reinterpret_cast<const float4*>(&Bs[buf][k][tx * 8 + 4]);
#pragma unroll
            for (int i = 0; i < 8; i++)
#pragma unroll
                for (int j = 0; j < 8; j++)
                    acc[i][j] += a[i] * b[j];
        }
        buf ^= 1;
    }
    float4 bv0 = *reinterpret_cast<const float4*>(bias + n0 + tx * 8);
    float4 bv1 = *reinterpret_cast<const float4*>(bias + n0 + tx * 8 + 4);
#pragma unroll
    for (int i = 0; i < 8; i++) {
        float4 o0, o1;
        o0.x = fmaxf(acc[i][0] + bv0.x, 0.f);
        o0.y = fmaxf(acc[i][1] + bv0.y, 0.f);
        o0.z = fmaxf(acc[i][2] + bv0.z, 0.f);
        o0.w = fmaxf(acc[i][3] + bv0.w, 0.f);
        o1.x = fmaxf(acc[i][4] + bv1.x, 0.f);
        o1.y = fmaxf(acc[i][5] + bv1.y, 0.f);
        o1.z = fmaxf(acc[i][6] + bv1.z, 0.f);
        o1.w = fmaxf(acc[i][7] + bv1.w, 0.f);
        float* crow = C + (size_t)(m0 + ty * 8 + i) * N + n0 + tx * 8;
        *reinterpret_cast<float4*>(crow)     = o0;
        *reinterpret_cast<float4*>(crow + 4) = o1;
    }
}

// ---------------- max pools ----------------
__global__ void maxpool1_kernel() {
    int i = blockIdx.x * blockDim.x + threadIdx.x;   // < 2048*128
    int s = i >> 7, c = i & 127;
    const float* base = &g_bufC[(size_t)s * 32 * 128 + c];
    float v = base[0];
#pragma unroll
    for (int k = 1; k < 32; k++) v = fmaxf(v, base[(size_t)k * 128]);
    g_f1[i] = v;
}
__global__ void maxpool2_kernel() {
    int i = blockIdx.x * blockDim.x + threadIdx.x;   // < 512*256
    int s = i >> 8, c = i & 255;
    const float* base = &g_bufD[(size_t)s * 64 * 256 + c];
    float v = base[0];
#pragma unroll
    for (int k = 1; k < 64; k++) v = fmaxf(v, base[(size_t)k * 256]);
    g_f2[i] = v;
}
__global__ void finalmax_kernel(float* __restrict__ out) {
    int c = blockIdx.x * blockDim.x + threadIdx.x;
    if (c >= 1024) return;
    float v = g_bufC[c];
    for (int s = 1; s < 512; s++) v = fmaxf(v, g_bufC[(size_t)s * 1024 + c]);
    out[c] = v;
}

// ---------------- launch ----------------
extern "C" void kernel_launch(void* const* d_in, const int* in_sizes, int n_in,
                              void* d_out, int out_size) {
    const float* points = (const float*)d_in[0];
    const float* prop   = (const float*)d_in[1];

    // Input binding: runtime-detect tensor ordering (dict-interleaved vs signature).
    const float *w10, *w11, *w12, *b10, *b11, *b12;
    const float *w20, *w21, *w22, *b20, *b21, *b22;
    const float *w30, *w31, *w32, *b30, *b31, *b32;
    if (in_sizes[3] == 64) {
        w10 = (const float*)d_in[2];  b10 = (const float*)d_in[3];
        w11 = (const float*)d_in[4];  b11 = (const float*)d_in[5];
        w12 = (const float*)d_in[6];  b12 = (const float*)d_in[7];
        w20 = (const float*)d_in[8];  b20 = (const float*)d_in[9];
        w21 = (const float*)d_in[10]; b21 = (const float*)d_in[11];
        w22 = (const float*)d_in[12]; b22 = (const float*)d_in[13];
        w30 = (const float*)d_in[14]; b30 = (const float*)d_in[15];
        w31 = (const float*)d_in[16]; b31 = (const float*)d_in[17];
        w32 = (const float*)d_in[18]; b32 = (const float*)d_in[19];
    } else {
        w10 = (const float*)d_in[2];  w11 = (const float*)d_in[3];  w12 = (const float*)d_in[4];
        b10 = (const float*)d_in[5];  b11 = (const float*)d_in[6];  b12 = (const float*)d_in[7];
        w20 = (const float*)d_in[8];  w21 = (const float*)d_in[9];  w22 = (const float*)d_in[10];
        b20 = (const float*)d_in[11]; b21 = (const float*)d_in[12]; b22 = (const float*)d_in[13];
        w30 = (const float*)d_in[14]; w31 = (const float*)d_in[15]; w32 = (const float*)d_in[16];
        b30 = (const float*)d_in[17]; b31 = (const float*)d_in[18]; b32 = (const float*)d_in[19];
    }
    float* out = (float*)d_out;

    float *h0, *bufA, *bufB, *bufC, *bufD, *wp, *a3;
    cudaGetSymbolAddress((void**)&h0,    g_h0);
    cudaGetSymbolAddress((void**)&bufA,  g_bufA);
    cudaGetSymbolAddress((void**)&bufB,  g_bufB);
    cudaGetSymbolAddress((void**)&bufC,  g_bufC);
    cudaGetSymbolAddress((void**)&bufD,  g_bufD);
    cudaGetSymbolAddress((void**)&wp,    g_wp);
    cudaGetSymbolAddress((void**)&a3,    g_a3);

    cudaFuncSetAttribute(fps1_kernel,
                         cudaFuncAttributeMaxDynamicSharedMemorySize, 65536);

    // stage 0 (also zeroes FPS1 packets -> replay-safe)
    prep_kernel<<<N0 / 256, 256>>>(points, prop);
    padw_all_kernel<<<(64*16 + 128*144 + 256*272 + 255) / 256, 256>>>(w10, w20, w30);

    // SA1 (fps1 writes g_newxyz1 directly)
    fps1_kernel<<<8, 1024, 65536>>>();
    bq1_fps2_kernel<<<257, 256>>>();                 // bq1 || fps2
    group1_bq2_kernel<<<320, 256>>>();               // group1 || bq2
    {
        dim3 g1(65536 / 128, 1);  gemm_bias_relu<<<g1, 128>>>(h0,   wp + WP1_OFF, b10, bufA, 65536, 64, 16);
        dim3 g2(65536 / 128, 1);  gemm_bias_relu<<<g2, 128>>>(bufA, w11,          b11, bufB, 65536, 64, 64);
        dim3 g3(65536 / 128, 2);  gemm_bias_relu<<<g3, 128>>>(bufB, w12,          b12, bufC, 65536, 128, 64);
    }
    maxpool1_kernel<<<(NP1 * 128 + 255) / 256, 256>>>();

    // SA2
    group2_kernel<<<(NP2 * NS2 + 255) / 256, 256>>>();
    {
        dim3 g4(32768 / 128, 2);  gemm_bias_relu<<<g4, 128>>>(bufC, wp + WP2_OFF, b20, bufA, 32768, 128, 144);
        dim3 g5(32768 / 128, 2);  gemm_bias_relu<<<g5, 128>>>(bufA, w21,          b21, bufB, 32768, 128, 128);
        dim3 g6(32768 / 128, 4);  gemm_bias_relu<<<g6, 128>>>(bufB, w22,          b22, bufD, 32768, 256, 128);
    }
    maxpool2_kernel<<<(NP2 * 256 + 255) / 256, 256>>>();

    // SA3
    a3_kernel<<<(NP2 * 272 + 255) / 256, 256>>>();
    {
        dim3 g7(512 / 128, 4);    gemm_bias_relu<<<g7, 128>>>(a3,   wp + WP3_OFF, b30, bufA, 512, 256, 272);
        dim3 g8(512 / 128, 8);    gemm_bias_relu<<<g8, 128>>>(bufA, w31,          b31, bufB, 512, 512, 256);
        dim3 g9(512 / 128, 16);   gemm_bias_relu<<<g9, 128>>>(bufB, w32,          b32, bufC, 512, 1024, 512);
    }
    finalmax_kernel<<<4, 256>>>(out);
}

// round 13
// speedup vs baseline: 1.2038x; 1.0060x over previous
#include <cuda_runtime.h>
#include <stdint.h>
#include <stddef.h>

#define N0   32768
#define NP1  2048
#define NS1  32
#define NP2  512
#define NS2  64

// ---------------- static scratch (no runtime allocation allowed) ----------------
__device__ float4 g_xyz[N0];
__device__ float  g_feats[N0 * 12];
__device__ float4 g_newxyz1[NP1];
__device__ int    g_gidx1[NP1 * NS1];
__device__ float  g_h0[NP1 * NS1 * 16];            // SA1 L0 input, K 15->16
__device__ float  g_bufA[65536 * 64];              // 16 MB
__device__ float  g_bufB[65536 * 64];              // 16 MB
__device__ float  g_bufC[65536 * 128];             // 32 MB
__device__ float  g_bufD[32768 * 256];             // 32 MB
__device__ float  g_f1[NP1 * 128];
__device__ float4 g_newxyz2[NP2];
__device__ int    g_gidx2[NP2 * NS2];
__device__ float  g_f2[NP2 * 256];
__device__ float  g_a3[NP2 * 272];                 // SA3 input, K 259->272
__device__ float  g_wp[64*16 + 128*144 + 256*272]; // padded weights
// FPS1 packets: [parity][block] -> 128-byte slot (uint4[8]);
// chunk0 = (tag,val,idx,_), chunk1 = (tag,cx,cy,cz). Dual-tag: reader accepts
// only when BOTH chunks carry the tag -> no write-ordering fence needed.
__device__ uint4  g_pk2[2][16][8];

#define WP1_OFF 0
#define WP2_OFF (64*16)
#define WP3_OFF (64*16 + 128*144)
#define PADW_TOTAL (64*16 + 128*144 + 256*272)

// ---------------- helpers ----------------
__device__ __forceinline__ uint4 ldv4(const uint4* p) {
    uint4 v;
    asm volatile("ld.volatile.global.v4.u32 {%0,%1,%2,%3}, [%4];"
                 : "=r"(v.x), "=r"(v.y), "=r"(v.z), "=r"(v.w) : "l"(p));
    return v;
}
__device__ __forceinline__ void stv4(uint4* p, uint4 v) {
    asm volatile("st.volatile.global.v4.u32 [%0], {%1,%2,%3,%4};"
                 :: "l"(p), "r"(v.x), "r"(v.y), "r"(v.z), "r"(v.w) : "memory");
}
// square-then-add (no FMA) to mirror XLA's elementwise (x-c)**2 then reduce
__device__ __forceinline__ float sqdist(float px, float py, float pz,
                                        float cx, float cy, float cz) {
    float dx = __fsub_rn(px, cx), dy = __fsub_rn(py, cy), dz = __fsub_rn(pz, cz);
    return __fadd_rn(__fadd_rn(__fmul_rn(dx, dx), __fmul_rn(dy, dy)), __fmul_rn(dz, dz));
}
// warp argmax over non-negative floats (bits order-isomorphic), tie -> min index.
__device__ __forceinline__ void warp_argmax(unsigned vbits, unsigned idx,
                                            unsigned& maxbits, unsigned& minidx) {
    maxbits = __reduce_max_sync(0xffffffffu, vbits);
    minidx  = __reduce_min_sync(0xffffffffu, (vbits == maxbits) ? idx : 0xffffffffu);
}

// -------- stage 0 fused: xyz + feats + weight padding + packet zeroing ----------
__global__ void prep_padw_kernel(const float* __restrict__ pts,
                                 const float* __restrict__ prop,
                                 const float* __restrict__ W1,
                                 const float* __restrict__ W2,
                                 const float* __restrict__ W3) {
    int i = blockIdx.x * blockDim.x + threadIdx.x;
    if (blockIdx.x == 0 && threadIdx.x < 256)
        ((uint4*)g_pk2)[threadIdx.x] = make_uint4(0u, 0u, 0u, 0u);
    if (i < N0) {
        float x = prop[0], y = prop[1], w = prop[3];
        float hw = __fmul_rn(w, 0.5f);
        float px = pts[i * 3 + 0], py = pts[i * 3 + 1], pz = pts[i * 3 + 2];
        float ax = __fsub_rn(px, x), ay = __fsub_rn(py, y);
        g_xyz[i] = make_float4(ax, ay, pz, 0.f);
        float oxp = __fadd_rn(x, hw), oxm = __fsub_rn(x, hw);
        float oyp = __fadd_rn(y, hw), oym = __fsub_rn(y, hw);
        float* f = &g_feats[(size_t)i * 12];
        f[0] = __fsub_rn(px, oxp); f[1]  = ay;                 f[2]  = pz;
        f[3] = __fsub_rn(px, oxm); f[4]  = ay;                 f[5]  = pz;
        f[6] = ax;                 f[7]  = __fsub_rn(py, oyp); f[8]  = pz;
        f[9] = ax;                 f[10] = __fsub_rn(py, oym); f[11] = pz;
    }
    if (i < 64 * 16) {
        int o = i / 16, k = i % 16;
        g_wp[i] = (k < 15) ? W1[(size_t)o * 15 + k] : 0.f;
    } else if (i < 64 * 16 + 128 * 144) {
        int j = i - 64 * 16;
        int o = j / 144, k = j % 144;
        g_wp[i] = (k < 131) ? W2[(size_t)o * 131 + k] : 0.f;
    } else if (i < PADW_TOTAL) {
        int j = i - (64 * 16 + 128 * 144);
        int o = j / 272, k = j % 272;
        g_wp[i] = (k < 259) ? W3[(size_t)o * 259 + k] : 0.f;
    }
}

// ------ FPS1: 8 blocks x 1024 thr, one poller warp, dual-tag packets ------------
__global__ void __launch_bounds__(1024) fps1_kernel() {
    extern __shared__ float4 sxyz[];       // 4096 pts = 64KB dynamic
    __shared__ float  sval[32];
    __shared__ int    sidx[32];
    __shared__ float4 sres[2];
    const int b = blockIdx.x, t = threadIdx.x;
    const int lane = t & 31, wp = t >> 5;
    const int base = b * 4096;
    float px[4], py[4], pz[4], dst[4];
#pragma unroll
    for (int j = 0; j < 4; j++) {
        float4 p = g_xyz[base + j * 1024 + t];
        sxyz[j * 1024 + t] = p;
        px[j] = p.x; py[j] = p.y; pz[j] = p.z; dst[j] = 1e10f;
    }
    float4 c0 = g_xyz[0];
    float ccx = c0.x, ccy = c0.y, ccz = c0.z;
    __syncthreads();

    for (int i = 0; i < NP1; i++) {
        if (b == 0 && t == 0)
            g_newxyz1[i] = make_float4(ccx, ccy, ccz, 0.f);
        if (i == NP1 - 1) break;

        float bv = -1.f; int bi = 0x7fffffff;
#pragma unroll
        for (int j = 0; j < 4; j++) {
            float d = sqdist(px[j], py[j], pz[j], ccx, ccy, ccz);
            dst[j] = fminf(dst[j], d);
            if (dst[j] > bv) { bv = dst[j]; bi = base + j * 1024 + t; }
        }
        unsigned wmax, widx;
        warp_argmax(__float_as_uint(bv), (unsigned)bi, wmax, widx);
        if (lane == 0) { sval[wp] = __uint_as_float(wmax); sidx[wp] = (int)widx; }
        __syncthreads();

        const int par = i & 1;
        if (wp == 0) {
            const unsigned tag = (unsigned)(i + 1);
            uint4 (*buf)[8] = g_pk2[par];

            unsigned vb = __float_as_uint(sval[lane]);
            unsigned ib = (unsigned)sidx[lane];
            unsigned bmax, bidx;
            warp_argmax(vb, ib, bmax, bidx);
            if (lane == 0) {
                float4 wn = sxyz[bidx - base];
                stv4(&buf[b][1], make_uint4(tag, __float_as_uint(wn.x),
                                            __float_as_uint(wn.y),
                                            __float_as_uint(wn.z)));
                stv4(&buf[b][0], make_uint4(tag, bmax, bidx, 0u));
            }

            bool  done = (lane >= 8);
            unsigned v2b = 0u, id2 = 0xffffffffu;
            float cxr = 0.f, cyr = 0.f, czr = 0.f;
            while (!__all_sync(0xffffffffu, done)) {
                if (!done) {
                    uint4 p = ldv4(&buf[lane][0]);
                    uint4 q = ldv4(&buf[lane][1]);
                    if (p.x == tag && q.x == tag) {
                        v2b = p.y; id2 = p.z;
                        cxr = __uint_as_float(q.y);
                        cyr = __uint_as_float(q.z);
                        czr = __uint_as_float(q.w);
                        done = true;
                    }
                }
            }
            unsigned gmax, gidx;
            warp_argmax(v2b, id2, gmax, gidx);
            int curn = (int)gidx;
            int wb   = curn >> 12;                 // 4096 pts per block
            float nx = __shfl_sync(0xffffffffu, cxr, wb);
            float ny = __shfl_sync(0xffffffffu, cyr, wb);
            float nz = __shfl_sync(0xffffffffu, czr, wb);
            if (lane == 0) sres[par] = make_float4(nx, ny, nz, 0.f);
        }
        __syncthreads();
        float4 r = sres[par];
        ccx = r.x; ccy = r.y; ccz = r.z;
    }
}

// ------ ball query body (warp/center, 8x MLP scan) — used by bq2 ----------------
__device__ __forceinline__ void ballquery_body(
    const float4* __restrict__ pts, int n, const float4* __restrict__ centers,
    int rows, float r2, int nsample, int* __restrict__ gidx, int gw, int lane)
{
    if (gw >= rows) return;
    float4 c = centers[gw];
    int found = 0, first = 0;
    int* out = &gidx[(size_t)gw * nsample];
    for (int base = 0; base < n; base += 256) {
        float4 p[8];
#pragma unroll
        for (int s = 0; s < 8; s++) p[s] = pts[base + s * 32 + lane];
        unsigned mm[8]; bool ii[8];
#pragma unroll
        for (int s = 0; s < 8; s++) {
            ii[s] = sqdist(p[s].x, p[s].y, p[s].z, c.x, c.y, c.z) <= r2;
            mm[s] = __ballot_sync(0xffffffffu, ii[s]);
        }
#pragma unroll
        for (int s = 0; s < 8; s++) {
            unsigned m = mm[s];
            if (found == 0 && m) first = base + s * 32 + __ffs(m) - 1;
            int pos = found + __popc(m & ((1u << lane) - 1u));
            if (ii[s] && pos < nsample) out[pos] = base + s * 32 + lane;
            found += __popc(m);
        }
        if (found >= nsample) break;
    }
    for (int p2 = found + lane; p2 < nsample; p2 += 32) out[p2] = first;
}

// ------ bq1: block-cooperative smem-staged scan, 16 centers per 512-thr block ----
__device__ void bq1_block_body() {
    __shared__ float4 spts[512];
    const int t = threadIdx.x, lane = t & 31, w = t >> 5;
    const int gw = blockIdx.x * 16 + w;              // < 2048 always
    const float r2 = (float)(0.4 * 0.4);
    float4 c = g_newxyz1[gw];
    int found = 0, first = 0;
    int* out = &g_gidx1[(size_t)gw * NS1];
    bool mydone = false;
    for (int base = 0; base < N0; base += 512) {
        spts[t] = g_xyz[base + t];
        __syncthreads();
        if (!mydone) {
#pragma unroll
            for (int s = 0; s < 16; s++) {
                float4 p = spts[s * 32 + lane];
                bool in = sqdist(p.x, p.y, p.z, c.x, c.y, c.z) <= r2;
                unsigned m = __ballot_sync(0xffffffffu, in);
                if (found == 0 && m) first = base + s * 32 + __ffs(m) - 1;
                int pos = found + __popc(m & ((1u << lane) - 1u));
                if (in && pos < NS1) out[pos] = base + s * 32 + lane;
                found += __popc(m);
            }
            if (found >= NS1) mydone = true;
        }
        if (__syncthreads_and(mydone ? 1 : 0)) break;
    }
    for (int p2 = found + lane; p2 < NS1; p2 += 32) out[p2] = first;
}

// ------ FPS2 body: 512 threads, 4 pts/thread, REDUX argmax -----------------------
__device__ void fps2_body() {
    __shared__ float4 sx[NP1];
    __shared__ float  sval[2][16];
    __shared__ int    sidx[2][16];
    const int t = threadIdx.x, lane = t & 31, w = t >> 5;
    for (int i = t; i < NP1; i += 512) sx[i] = g_newxyz1[i];
    __syncthreads();
    float px[4], py[4], pz[4], dst[4];
#pragma unroll
    for (int j = 0; j < 4; j++) {
        float4 p = sx[j * 512 + t];
        px[j] = p.x; py[j] = p.y; pz[j] = p.z; dst[j] = 1e10f;
    }
    int cur = 0;
    for (int i = 0; i < NP2; i++) {
        if (t == 0) {
            float4 c = sx[cur];
            g_newxyz2[i] = make_float4(c.x, c.y, c.z, 0.f);
        }
        if (i == NP2 - 1) break;
        float4 c = sx[cur];
        float bv = -1.f; int bi = 0x7fffffff;
#pragma unroll
        for (int j = 0; j < 4; j++) {
            float d = sqdist(px[j], py[j], pz[j], c.x, c.y, c.z);
            dst[j] = fminf(dst[j], d);
            if (dst[j] > bv) { bv = dst[j]; bi = j * 512 + t; }
        }
        unsigned wmax, widx;
        warp_argmax(__float_as_uint(bv), (unsigned)bi, wmax, widx);
        int par = i & 1;
        if (lane == 0) { sval[par][w] = __uint_as_float(wmax); sidx[par][w] = (int)widx; }
        __syncthreads();
        unsigned vb = (lane < 16) ? __float_as_uint(sval[par][lane]) : 0u;
        unsigned ib = (lane < 16) ? (unsigned)sidx[par][lane] : 0xffffffffu;
        unsigned bmax, bidx;
        warp_argmax(vb, ib, bmax, bidx);
        cur = (int)bidx;
    }
}

// ------ fused launch 1: bq1 (blocks 0-127) || fps2 (block 128), 512 threads ------
__global__ void __launch_bounds__(512) bq1_fps2_kernel() {
    if (blockIdx.x < 128) {
        bq1_block_body();
    } else {
        fps2_body();
    }
}

// ------ fused launch 2: group1 (blocks 0-255) || bq2 (blocks 256-319) ------------
__global__ void __launch_bounds__(256) group1_bq2_kernel() {
    if (blockIdx.x < 256) {
        int m = blockIdx.x * 256 + threadIdx.x;      // < 65536
        int s = m >> 5;
        int g = g_gidx1[m];
        float4 p = g_xyz[g], c = g_newxyz1[s];
        float* o = &g_h0[(size_t)m * 16];
        o[0] = __fsub_rn(p.x, c.x); o[1] = __fsub_rn(p.y, c.y); o[2] = __fsub_rn(p.z, c.z);
        const float* f = &g_feats[(size_t)g * 12];
#pragma unroll
        for (int j = 0; j < 12; j++) o[3 + j] = f[j];
        o[15] = 0.f;
    } else {
        int gw = (blockIdx.x - 256) * 8 + (threadIdx.x >> 5);
        ballquery_body(g_newxyz1, NP1, g_newxyz2, NP2, (float)(0.8 * 0.8), NS2,
                       g_gidx2, gw, threadIdx.x & 31);
    }
}

// ---------------- grouping 2 ----------------
__global__ void group2_kernel() {
    int m = blockIdx.x * blockDim.x + threadIdx.x;   // < 32768
    int s = m >> 6;
    int g = g_gidx2[m];
    float4 p = g_newxyz1[g], c = g_newxyz2[s];
    float* o = &g_bufC[(size_t)m * 144];
    o[0] = __fsub_rn(p.x, c.x); o[1] = __fsub_rn(p.y, c.y); o[2] = __fsub_rn(p.z, c.z);
    const float* f = &g_f1[(size_t)g * 128];
#pragma unroll 4
    for (int j = 0; j < 128; j++) o[3 + j] = f[j];
#pragma unroll
    for (int j = 131; j < 144; j++) o[j] = 0.f;
}

__global__ void a3_kernel() {
    int i = blockIdx.x * blockDim.x + threadIdx.x;
    if (i >= NP2 * 272) return;
    int s = i / 272, c = i % 272;
    float v;
    if (c < 3)        { float4 p = g_newxyz2[s]; v = (c == 0) ? p.x : ((c == 1) ? p.y : p.z); }
    else if (c < 259)   v = g_f2[(size_t)s * 256 + (c - 3)];
    else                v = 0.f;
    g_a3[i] = v;
}

// -------- SGEMM: 128 threads, tile 128x64, 8x8 micro, double-buffered smem.
// C[M,N] = relu(A[M,K] * W[N,K]^T + bias), M%128==0, N%64==0, K%16==0
__global__ void __launch_bounds__(128) gemm_bias_relu(
    const float* __restrict__ A, const float* __restrict__ W,
    const float* __restrict__ bias, float* __restrict__ C,
    int M, int N, int K)
{
    __shared__ float As[2][16][132];
    __shared__ float Bs[2][16][68];
    const int m0 = blockIdx.x * 128;
    const int n0 = blockIdx.y * 64;
    const int tid = threadIdx.x;
    const int tx = tid & 7, ty = tid >> 3;
    const int brow = tid >> 1, bc8 = (tid & 1) << 3;
    float acc[8][8];
#pragma unroll
    for (int i = 0; i < 8; i++)
#pragma unroll
        for (int j = 0; j < 8; j++) acc[i][j] = 0.f;

    const float* Ap = A + (size_t)(m0 + tid) * K;
    const float* Wp = W + (size_t)(n0 + brow) * K + bc8;

    float4 a0 = *reinterpret_cast<const float4*>(Ap);
    float4 a1 = *reinterpret_cast<const float4*>(Ap + 4);
    float4 a2 = *reinterpret_cast<const float4*>(Ap + 8);
    float4 a3 = *reinterpret_cast<const float4*>(Ap + 12);
    float4 w0 = *reinterpret_cast<const float4*>(Wp);
    float4 w1 = *reinterpret_cast<const float4*>(Wp + 4);

    int buf = 0;
    for (int k0 = 0; k0 < K; k0 += 16) {
        As[buf][0][tid]  = a0.x; As[buf][1][tid]  = a0.y; As[buf][2][tid]  = a0.z; As[buf][3][tid]  = a0.w;
        As[buf][4][tid]  = a1.x; As[buf][5][tid]  = a1.y; As[buf][6][tid]  = a1.z; As[buf][7][tid]  = a1.w;
        As[buf][8][tid]  = a2.x; As[buf][9][tid]  = a2.y; As[buf][10][tid] = a2.z; As[buf][11][tid] = a2.w;
        As[buf][12][tid] = a3.x; As[buf][13][tid] = a3.y; As[buf][14][tid] = a3.z; As[buf][15][tid] = a3.w;
        Bs[buf][bc8 + 0][brow] = w0.x; Bs[buf][bc8 + 1][brow] = w0.y;
        Bs[buf][bc8 + 2][brow] = w0.z; Bs[buf][bc8 + 3][brow] = w0.w;
        Bs[buf][bc8 + 4][brow] = w1.x; Bs[buf][bc8 + 5][brow] = w1.y;
        Bs[buf][bc8 + 6][brow] = w1.z; Bs[buf][bc8 + 7][brow] = w1.w;
        __syncthreads();

        if (k0 + 16 < K) {
            a0 = *reinterpret_cast<const float4*>(Ap + k0 + 16);
            a1 = *reinterpret_cast<const float4*>(Ap + k0 + 20);
            a2 = *reinterpret_cast<const float4*>(Ap + k0 + 24);
            a3 = *reinterpret_cast<const float4*>(Ap + k0 + 28);
            w0 = *reinterpret_cast<const float4*>(Wp + k0 + 16);
            w1 = *reinterpret_cast<const float4*>(Wp + k0 + 20);
        }
#pragma unroll
        for (int k = 0; k < 16; k++) {
            float a[8], b[8];
            *reinterpret_cast<float4*>(&a[0]) = *reinterpret_cast<const float4*>(&As[buf][k][ty * 8]);
            *reinterpret_cast<float4*>(&a[4]) = *reinterpret_cast<const float4*>(&As[buf][k][ty * 8 + 4]);
            *reinterpret_cast<float4*>(&b[0]) = *reinterpret_cast<const float4*>(&Bs[buf][k][tx * 8]);
            *reinterpret_cast<float4*>(&b[4]) = *reinterpret_cast<const float4*>(&Bs[buf][k][tx * 8 + 4]);
#pragma unroll
            for (int i = 0; i < 8; i++)
#pragma unroll
                for (int j = 0; j < 8; j++)
                    acc[i][j] += a[i] * b[j];
        }
        buf ^= 1;
    }
    float4 bv0 = *reinterpret_cast<const float4*>(bias + n0 + tx * 8);
    float4 bv1 = *reinterpret_cast<const float4*>(bias + n0 + tx * 8 + 4);
#pragma unroll
    for (int i = 0; i < 8; i++) {
        float4 o0, o1;
        o0.x = fmaxf(acc[i][0] + bv0.x, 0.f);
        o0.y = fmaxf(acc[i][1] + bv0.y, 0.f);
        o0.z = fmaxf(acc[i][2] + bv0.z, 0.f);
        o0.w = fmaxf(acc[i][3] + bv0.w, 0.f);
        o1.x = fmaxf(acc[i][4] + bv1.x, 0.f);
        o1.y = fmaxf(acc[i][5] + bv1.y, 0.f);
        o1.z = fmaxf(acc[i][6] + bv1.z, 0.f);
        o1.w = fmaxf(acc[i][7] + bv1.w, 0.f);
        float* crow = C + (size_t)(m0 + ty * 8 + i) * N + n0 + tx * 8;
        *reinterpret_cast<float4*>(crow)     = o0;
        *reinterpret_cast<float4*>(crow + 4) = o1;
    }
}

// ---------------- max pools ----------------
__global__ void maxpool1_kernel() {
    int i = blockIdx.x * blockDim.x + threadIdx.x;   // < 2048*128
    int s = i >> 7, c = i & 127;
    const float* base = &g_bufC[(size_t)s * 32 * 128 + c];
    float v = base[0];
#pragma unroll
    for (int k = 1; k < 32; k++) v = fmaxf(v, base[(size_t)k * 128]);
    g_f1[i] = v;
}
__global__ void maxpool2_kernel() {
    int i = blockIdx.x * blockDim.x + threadIdx.x;   // < 512*256
    int s = i >> 8, c = i & 255;
    const float* base = &g_bufD[(size_t)s * 64 * 256 + c];
    float v = base[0];
#pragma unroll
    for (int k = 1; k < 64; k++) v = fmaxf(v, base[(size_t)k * 256]);
    g_f2[i] = v;
}
__global__ void finalmax_kernel(float* __restrict__ out) {
    int c = blockIdx.x * blockDim.x + threadIdx.x;
    if (c >= 1024) return;
    float v = g_bufC[c];
    for (int s = 1; s < 512; s++) v = fmaxf(v, g_bufC[(size_t)s * 1024 + c]);
    out[c] = v;
}

// ---------------- launch ----------------
extern "C" void kernel_launch(void* const* d_in, const int* in_sizes, int n_in,
                              void* d_out, int out_size) {
    const float* points = (const float*)d_in[0];
    const float* prop   = (const float*)d_in[1];

    // Input binding: runtime-detect tensor ordering (dict-interleaved vs signature).
    const float *w10, *w11, *w12, *b10, *b11, *b12;
    const float *w20, *w21, *w22, *b20, *b21, *b22;
    const float *w30, *w31, *w32, *b30, *b31, *b32;
    if (in_sizes[3] == 64) {
        w10 = (const float*)d_in[2];  b10 = (const float*)d_in[3];
        w11 = (const float*)d_in[4];  b11 = (const float*)d_in[5];
        w12 = (const float*)d_in[6];  b12 = (const float*)d_in[7];
        w20 = (const float*)d_in[8];  b20 = (const float*)d_in[9];
        w21 = (const float*)d_in[10]; b21 = (const float*)d_in[11];
        w22 = (const float*)d_in[12]; b22 = (const float*)d_in[13];
        w30 = (const float*)d_in[14]; b30 = (const float*)d_in[15];
        w31 = (const float*)d_in[16]; b31 = (const float*)d_in[17];
        w32 = (const float*)d_in[18]; b32 = (const float*)d_in[19];
    } else {
        w10 = (const float*)d_in[2];  w11 = (const float*)d_in[3];  w12 = (const float*)d_in[4];
        b10 = (const float*)d_in[5];  b11 = (const float*)d_in[6];  b12 = (const float*)d_in[7];
        w20 = (const float*)d_in[8];  w21 = (const float*)d_in[9];  w22 = (const float*)d_in[10];
        b20 = (const float*)d_in[11]; b21 = (const float*)d_in[12]; b22 = (const float*)d_in[13];
        w30 = (const float*)d_in[14]; w31 = (const float*)d_in[15]; w32 = (const float*)d_in[16];
        b30 = (const float*)d_in[17]; b31 = (const float*)d_in[18]; b32 = (const float*)d_in[19];
    }
    float* out = (float*)d_out;

    float *h0, *bufA, *bufB, *bufC, *bufD, *wp, *a3;
    cudaGetSymbolAddress((void**)&h0,    g_h0);
    cudaGetSymbolAddress((void**)&bufA,  g_bufA);
    cudaGetSymbolAddress((void**)&bufB,  g_bufB);
    cudaGetSymbolAddress((void**)&bufC,  g_bufC);
    cudaGetSymbolAddress((void**)&bufD,  g_bufD);
    cudaGetSymbolAddress((void**)&wp,    g_wp);
    cudaGetSymbolAddress((void**)&a3,    g_a3);

    cudaFuncSetAttribute(fps1_kernel,
                         cudaFuncAttributeMaxDynamicSharedMemorySize, 65536);

    // stage 0 (fused prep + weight padding; also zeroes FPS1 packets)
    prep_padw_kernel<<<(PADW_TOTAL + 255) / 256, 256>>>(points, prop, w10, w20, w30);

    // SA1 (fps1 writes g_newxyz1 directly)
    fps1_kernel<<<8, 1024, 65536>>>();
    bq1_fps2_kernel<<<129, 512>>>();                 // bq1 || fps2
    group1_bq2_kernel<<<320, 256>>>();               // group1 || bq2
    {
        dim3 g1(65536 / 128, 1);  gemm_bias_relu<<<g1, 128>>>(h0,   wp + WP1_OFF, b10, bufA, 65536, 64, 16);
        dim3 g2(65536 / 128, 1);  gemm_bias_relu<<<g2, 128>>>(bufA, w11,          b11, bufB, 65536, 64, 64);
        dim3 g3(65536 / 128, 2);  gemm_bias_relu<<<g3, 128>>>(bufB, w12,          b12, bufC, 65536, 128, 64);
    }
    maxpool1_kernel<<<(NP1 * 128 + 255) / 256, 256>>>();

    // SA2
    group2_kernel<<<(NP2 * NS2 + 255) / 256, 256>>>();
    {
        dim3 g4(32768 / 128, 2);  gemm_bias_relu<<<g4, 128>>>(bufC, wp + WP2_OFF, b20, bufA, 32768, 128, 144);
        dim3 g5(32768 / 128, 2);  gemm_bias_relu<<<g5, 128>>>(bufA, w21,          b21, bufB, 32768, 128, 128);
        dim3 g6(32768 / 128, 4);  gemm_bias_relu<<<g6, 128>>>(bufB, w22,          b22, bufD, 32768, 256, 128);
    }
    maxpool2_kernel<<<(NP2 * 256 + 255) / 256, 256>>>();

    // SA3
    a3_kernel<<<(NP2 * 272 + 255) / 256, 256>>>();
    {
        dim3 g7(512 / 128, 4);    gemm_bias_relu<<<g7, 128>>>(a3,   wp + WP3_OFF, b30, bufA, 512, 256, 272);
        dim3 g8(512 / 128, 8);    gemm_bias_relu<<<g8, 128>>>(bufA, w31,          b31, bufB, 512, 512, 256);
        dim3 g9(512 / 128, 16);   gemm_bias_relu<<<g9, 128>>>(bufB, w32,          b32, bufC, 512, 1024, 512);
    }
    finalmax_kernel<<<4, 256>>>(out);
}

// round 14
// speedup vs baseline: 1.2492x; 1.0377x over previous
#include <cuda_runtime.h>
#include <stdint.h>
#include <stddef.h>

#define N0   32768
#define NP1  2048
#define NS1  32
#define NP2  512
#define NS2  64

// ---------------- static scratch (no runtime allocation allowed) ----------------
__device__ float4 g_xyz[N0];
__device__ float  g_feats[N0 * 12];
__device__ float4 g_newxyz1[NP1];                  // w = iteration tag (nonzero when ready)
__device__ int    g_gidx1[NP1 * NS1];
__device__ float  g_h0[NP1 * NS1 * 16];            // SA1 L0 input, K 15->16
__device__ float  g_bufA[65536 * 64];              // 16 MB
__device__ float  g_bufB[65536 * 64];              // 16 MB
__device__ float  g_bufC[65536 * 128];             // 32 MB
__device__ float  g_bufD[32768 * 256];             // 32 MB
__device__ float  g_f1[NP1 * 128];
__device__ float4 g_newxyz2[NP2];
__device__ int    g_gidx2[NP2 * NS2];
__device__ float  g_f2[NP2 * 256];
__device__ float  g_a3[NP2 * 272];                 // SA3 input, K 259->272
__device__ float  g_wp[64*16 + 128*144 + 256*272]; // padded weights
// FPS1 packets: [parity][block] -> 128-byte slot (uint4[8]);
// chunk0 = (tag,val,idx,_), chunk1 = (tag,cx,cy,cz). Dual-tag: reader accepts
// only when BOTH chunks carry the tag -> no write-ordering fence needed.
__device__ uint4  g_pk2[2][16][8];

#define WP1_OFF 0
#define WP2_OFF (64*16)
#define WP3_OFF (64*16 + 128*144)
#define PADW_TOTAL (64*16 + 128*144 + 256*272)

// ---------------- helpers ----------------
__device__ __forceinline__ uint4 ldv4(const uint4* p) {
    uint4 v;
    asm volatile("ld.volatile.global.v4.u32 {%0,%1,%2,%3}, [%4];"
                 : "=r"(v.x), "=r"(v.y), "=r"(v.z), "=r"(v.w) : "l"(p));
    return v;
}
__device__ __forceinline__ void stv4(uint4* p, uint4 v) {
    asm volatile("st.volatile.global.v4.u32 [%0], {%1,%2,%3,%4};"
                 :: "l"(p), "r"(v.x), "r"(v.y), "r"(v.z), "r"(v.w) : "memory");
}
// square-then-add (no FMA) to mirror XLA's elementwise (x-c)**2 then reduce
__device__ __forceinline__ float sqdist(float px, float py, float pz,
                                        float cx, float cy, float cz) {
    float dx = __fsub_rn(px, cx), dy = __fsub_rn(py, cy), dz = __fsub_rn(pz, cz);
    return __fadd_rn(__fadd_rn(__fmul_rn(dx, dx), __fmul_rn(dy, dy)), __fmul_rn(dz, dz));
}
// warp argmax over non-negative floats (bits order-isomorphic), tie -> min index.
__device__ __forceinline__ void warp_argmax(unsigned vbits, unsigned idx,
                                            unsigned& maxbits, unsigned& minidx) {
    maxbits = __reduce_max_sync(0xffffffffu, vbits);
    minidx  = __reduce_min_sync(0xffffffffu, (vbits == maxbits) ? idx : 0xffffffffu);
}

// -------- stage 0 fused: xyz + feats + weight padding + tag/packet zeroing ------
__global__ void prep_padw_kernel(const float* __restrict__ pts,
                                 const float* __restrict__ prop,
                                 const float* __restrict__ W1,
                                 const float* __restrict__ W2,
                                 const float* __restrict__ W3) {
    int i = blockIdx.x * blockDim.x + threadIdx.x;
    if (blockIdx.x == 0 && threadIdx.x < 256)
        ((uint4*)g_pk2)[threadIdx.x] = make_uint4(0u, 0u, 0u, 0u);
    if (i < NP1)
        reinterpret_cast<float*>(&g_newxyz1[i])[3] = 0.f;   // clear ready tags (replay)
    if (i < N0) {
        float x = prop[0], y = prop[1], w = prop[3];
        float hw = __fmul_rn(w, 0.5f);
        float px = pts[i * 3 + 0], py = pts[i * 3 + 1], pz = pts[i * 3 + 2];
        float ax = __fsub_rn(px, x), ay = __fsub_rn(py, y);
        g_xyz[i] = make_float4(ax, ay, pz, 0.f);
        float oxp = __fadd_rn(x, hw), oxm = __fsub_rn(x, hw);
        float oyp = __fadd_rn(y, hw), oym = __fsub_rn(y, hw);
        float* f = &g_feats[(size_t)i * 12];
        f[0] = __fsub_rn(px, oxp); f[1]  = ay;                 f[2]  = pz;
        f[3] = __fsub_rn(px, oxm); f[4]  = ay;                 f[5]  = pz;
        f[6] = ax;                 f[7]  = __fsub_rn(py, oyp); f[8]  = pz;
        f[9] = ax;                 f[10] = __fsub_rn(py, oym); f[11] = pz;
    }
    if (i < 64 * 16) {
        int o = i / 16, k = i % 16;
        g_wp[i] = (k < 15) ? W1[(size_t)o * 15 + k] : 0.f;
    } else if (i < 64 * 16 + 128 * 144) {
        int j = i - 64 * 16;
        int o = j / 144, k = j % 144;
        g_wp[i] = (k < 131) ? W2[(size_t)o * 131 + k] : 0.f;
    } else if (i < PADW_TOTAL) {
        int j = i - (64 * 16 + 128 * 144);
        int o = j / 272, k = j % 272;
        g_wp[i] = (k < 259) ? W3[(size_t)o * 259 + k] : 0.f;
    }
}

// ------ FPS1 body: 8 blocks x 1024 thr, one poller warp, dual-tag packets -------
// Emits centers as tagged volatile packets so concurrent bq1/fps2 blocks can consume.
__device__ void fps1_body(float4* sxyz) {
    __shared__ float  sval[32];
    __shared__ int    sidx[32];
    __shared__ float4 sres[2];
    const int b = blockIdx.x, t = threadIdx.x;
    const int lane = t & 31, wp = t >> 5;
    const int base = b * 4096;
    float px[4], py[4], pz[4], dst[4];
#pragma unroll
    for (int j = 0; j < 4; j++) {
        float4 p = g_xyz[base + j * 1024 + t];
        sxyz[j * 1024 + t] = p;
        px[j] = p.x; py[j] = p.y; pz[j] = p.z; dst[j] = 1e10f;
    }
    float4 c0 = g_xyz[0];
    float ccx = c0.x, ccy = c0.y, ccz = c0.z;
    __syncthreads();

    for (int i = 0; i < NP1; i++) {
        if (b == 0 && t == 0)
            stv4((uint4*)&g_newxyz1[i],
                 make_uint4(__float_as_uint(ccx), __float_as_uint(ccy),
                            __float_as_uint(ccz), (unsigned)(i + 1)));
        if (i == NP1 - 1) break;

        float bv = -1.f; int bi = 0x7fffffff;
#pragma unroll
        for (int j = 0; j < 4; j++) {
            float d = sqdist(px[j], py[j], pz[j], ccx, ccy, ccz);
            dst[j] = fminf(dst[j], d);
            if (dst[j] > bv) { bv = dst[j]; bi = base + j * 1024 + t; }
        }
        unsigned wmax, widx;
        warp_argmax(__float_as_uint(bv), (unsigned)bi, wmax, widx);
        if (lane == 0) { sval[wp] = __uint_as_float(wmax); sidx[wp] = (int)widx; }
        __syncthreads();

        const int par = i & 1;
        if (wp == 0) {
            const unsigned tag = (unsigned)(i + 1);
            uint4 (*buf)[8] = g_pk2[par];

            unsigned vb = __float_as_uint(sval[lane]);
            unsigned ib = (unsigned)sidx[lane];
            unsigned bmax, bidx;
            warp_argmax(vb, ib, bmax, bidx);
            if (lane == 0) {
                float4 wn = sxyz[bidx - base];
                stv4(&buf[b][1], make_uint4(tag, __float_as_uint(wn.x),
                                            __float_as_uint(wn.y),
                                            __float_as_uint(wn.z)));
                stv4(&buf[b][0], make_uint4(tag, bmax, bidx, 0u));
            }

            bool  done = (lane >= 8);
            unsigned v2b = 0u, id2 = 0xffffffffu;
            float cxr = 0.f, cyr = 0.f, czr = 0.f;
            while (!__all_sync(0xffffffffu, done)) {
                if (!done) {
                    uint4 p = ldv4(&buf[lane][0]);
                    uint4 q = ldv4(&buf[lane][1]);
                    if (p.x == tag && q.x == tag) {
                        v2b = p.y; id2 = p.z;
                        cxr = __uint_as_float(q.y);
                        cyr = __uint_as_float(q.z);
                        czr = __uint_as_float(q.w);
                        done = true;
                    }
                }
            }
            unsigned gmax, gidx;
            warp_argmax(v2b, id2, gmax, gidx);
            int curn = (int)gidx;
            int wb   = curn >> 12;                 // 4096 pts per block
            float nx = __shfl_sync(0xffffffffu, cxr, wb);
            float ny = __shfl_sync(0xffffffffu, cyr, wb);
            float nz = __shfl_sync(0xffffffffu, czr, wb);
            if (lane == 0) sres[par] = make_float4(nx, ny, nz, 0.f);
        }
        __syncthreads();
        float4 r = sres[par];
        ccx = r.x; ccy = r.y; ccz = r.z;
    }
}

// ------ ball query body (warp/center, 8x MLP scan) -------------------------------
__device__ __forceinline__ void ballquery_scan(
    const float4* __restrict__ pts, int n, float4 c,
    float r2, int nsample, int* __restrict__ out, int lane)
{
    int found = 0, first = 0;
    for (int base = 0; base < n; base += 256) {
        float4 p[8];
#pragma unroll
        for (int s = 0; s < 8; s++) p[s] = pts[base + s * 32 + lane];
        unsigned mm[8]; bool ii[8];
#pragma unroll
        for (int s = 0; s < 8; s++) {
            ii[s] = sqdist(p[s].x, p[s].y, p[s].z, c.x, c.y, c.z) <= r2;
            mm[s] = __ballot_sync(0xffffffffu, ii[s]);
        }
#pragma unroll
        for (int s = 0; s < 8; s++) {
            unsigned m = mm[s];
            if (found == 0 && m) first = base + s * 32 + __ffs(m) - 1;
            int pos = found + __popc(m & ((1u << lane) - 1u));
            if (ii[s] && pos < nsample) out[pos] = base + s * 32 + lane;
            found += __popc(m);
        }
        if (found >= nsample) break;
    }
    for (int p2 = found + lane; p2 < nsample; p2 += 32) out[p2] = first;
}

// ------ bq1 body: one warp per center, polls center ready-tag then scans --------
__device__ void bq1_flag_body(int bb) {
    const int lane = threadIdx.x & 31, w = threadIdx.x >> 5;
    const int gw = bb * 32 + w;                      // < 2048
    uint4 cp;
    do { cp = ldv4((uint4*)&g_newxyz1[gw]); } while (cp.w == 0u);
    float4 c = make_float4(__uint_as_float(cp.x), __uint_as_float(cp.y),
                           __uint_as_float(cp.z), 0.f);
    ballquery_scan(g_xyz, N0, c, (float)(0.4 * 0.4), NS1,
                   &g_gidx1[(size_t)gw * NS1], lane);
}

// ------ FPS2 body: 1024 threads, 2 pts/thread, polls all center tags first ------
__device__ void fps2_flag_body(float4* sx) {
    __shared__ float  sval[2][32];
    __shared__ int    sidx[2][32];
    const int t = threadIdx.x, lane = t & 31, w = t >> 5;
#pragma unroll
    for (int j = 0; j < 2; j++) {
        int idx = j * 1024 + t;
        uint4 cp;
        do { cp = ldv4((uint4*)&g_newxyz1[idx]); } while (cp.w == 0u);
        sx[idx] = make_float4(__uint_as_float(cp.x), __uint_as_float(cp.y),
                              __uint_as_float(cp.z), 0.f);
    }
    __syncthreads();
    float px[2], py[2], pz[2], dst[2];
#pragma unroll
    for (int j = 0; j < 2; j++) {
        float4 p = sx[j * 1024 + t];
        px[j] = p.x; py[j] = p.y; pz[j] = p.z; dst[j] = 1e10f;
    }
    int cur = 0;
    for (int i = 0; i < NP2; i++) {
        if (t == 0) {
            float4 c = sx[cur];
            g_newxyz2[i] = make_float4(c.x, c.y, c.z, 0.f);
        }
        if (i == NP2 - 1) break;
        float4 c = sx[cur];
        float bv = -1.f; int bi = 0x7fffffff;
#pragma unroll
        for (int j = 0; j < 2; j++) {
            float d = sqdist(px[j], py[j], pz[j], c.x, c.y, c.z);
            dst[j] = fminf(dst[j], d);
            if (dst[j] > bv) { bv = dst[j]; bi = j * 1024 + t; }
        }
        unsigned wmax, widx;
        warp_argmax(__float_as_uint(bv), (unsigned)bi, wmax, widx);
        int par = i & 1;
        if (lane == 0) { sval[par][w] = __uint_as_float(wmax); sidx[par][w] = (int)widx; }
        __syncthreads();
        unsigned vb = __float_as_uint(sval[par][lane]);
        unsigned ib = (unsigned)sidx[par][lane];
        unsigned bmax, bidx;
        warp_argmax(vb, ib, bmax, bidx);
        cur = (int)bidx;
    }
}

// ------ mega kernel: fps1 (0-7) || bq1 (8-71) || fps2 (72), 73 blocks resident ---
__global__ void __launch_bounds__(1024) mega_kernel() {
    extern __shared__ float4 dyn_smem[];             // fps1: 64KB pts; fps2: 32KB pts
    const int b = blockIdx.x;
    if (b < 8)       fps1_body(dyn_smem);
    else if (b < 72) bq1_flag_body(b - 8);
    else             fps2_flag_body(dyn_smem);
}

// ------ group1 (blocks 0-255) || bq2 (blocks 256-319) ----------------------------
__global__ void __launch_bounds__(256) group1_bq2_kernel() {
    if (blockIdx.x < 256) {
        int m = blockIdx.x * 256 + threadIdx.x;      // < 65536
        int s = m >> 5;
        int g = g_gidx1[m];
        float4 p = g_xyz[g], c = g_newxyz1[s];
        float* o = &g_h0[(size_t)m * 16];
        o[0] = __fsub_rn(p.x, c.x); o[1] = __fsub_rn(p.y, c.y); o[2] = __fsub_rn(p.z, c.z);
        const float* f = &g_feats[(size_t)g * 12];
#pragma unroll
        for (int j = 0; j < 12; j++) o[3 + j] = f[j];
        o[15] = 0.f;
    } else {
        int lane = threadIdx.x & 31;
        int gw = (blockIdx.x - 256) * 8 + (threadIdx.x >> 5);
        if (gw < NP2) {
            float4 cc = g_newxyz2[gw];
            ballquery_scan(g_newxyz1, NP1, cc, (float)(0.8 * 0.8), NS2,
                           &g_gidx2[(size_t)gw * NS2], lane);
        }
    }
}

// ---------------- grouping 2 ----------------
__global__ void group2_kernel() {
    int m = blockIdx.x * blockDim.x + threadIdx.x;   // < 32768
    int s = m >> 6;
    int g = g_gidx2[m];
    float4 p = g_newxyz1[g], c = g_newxyz2[s];
    float* o = &g_bufC[(size_t)m * 144];
    o[0] = __fsub_rn(p.x, c.x); o[1] = __fsub_rn(p.y, c.y); o[2] = __fsub_rn(p.z, c.z);
    const float* f = &g_f1[(size_t)g * 128];
#pragma unroll 4
    for (int j = 0; j < 128; j++) o[3 + j] = f[j];
#pragma unroll
    for (int j = 131; j < 144; j++) o[j] = 0.f;
}

__global__ void a3_kernel() {
    int i = blockIdx.x * blockDim.x + threadIdx.x;
    if (i >= NP2 * 272) return;
    int s = i / 272, c = i % 272;
    float v;
    if (c < 3)        { float4 p = g_newxyz2[s]; v = (c == 0) ? p.x : ((c == 1) ? p.y : p.z); }
    else if (c < 259)   v = g_f2[(size_t)s * 256 + (c - 3)];
    else                v = 0.f;
    g_a3[i] = v;
}

// -------- SGEMM: 128 threads, tile 128x64, 8x8 micro, double-buffered smem.
// C[M,N] = relu(A[M,K] * W[N,K]^T + bias), M%128==0, N%64==0, K%16==0
__global__ void __launch_bounds__(128) gemm_bias_relu(
    const float* __restrict__ A, const float* __restrict__ W,
    const float* __restrict__ bias, float* __restrict__ C,
    int M, int N, int K)
{
    __shared__ float As[2][16][132];
    __shared__ float Bs[2][16][68];
    const int m0 = blockIdx.x * 128;
    const int n0 = blockIdx.y * 64;
    const int tid = threadIdx.x;
    const int tx = tid & 7, ty = tid >> 3;
    const int brow = tid >> 1, bc8 = (tid & 1) << 3;
    float acc[8][8];
#pragma unroll
    for (int i = 0; i < 8; i++)
#pragma unroll
        for (int j = 0; j < 8; j++) acc[i][j] = 0.f;

    const float* Ap = A + (size_t)(m0 + tid) * K;
    const float* Wp = W + (size_t)(n0 + brow) * K + bc8;

    float4 a0 = *reinterpret_cast<const float4*>(Ap);
    float4 a1 = *reinterpret_cast<const float4*>(Ap + 4);
    float4 a2 = *reinterpret_cast<const float4*>(Ap + 8);
    float4 a3 = *reinterpret_cast<const float4*>(Ap + 12);
    float4 w0 = *reinterpret_cast<const float4*>(Wp);
    float4 w1 = *reinterpret_cast<const float4*>(Wp + 4);

    int buf = 0;
    for (int k0 = 0; k0 < K; k0 += 16) {
        As[buf][0][tid]  = a0.x; As[buf][1][tid]  = a0.y; As[buf][2][tid]  = a0.z; As[buf][3][tid]  = a0.w;
        As[buf][4][tid]  = a1.x; As[buf][5][tid]  = a1.y; As[buf][6][tid]  = a1.z; As[buf][7][tid]  = a1.w;
        As[buf][8][tid]  = a2.x; As[buf][9][tid]  = a2.y; As[buf][10][tid] = a2.z; As[buf][11][tid] = a2.w;
        As[buf][12][tid] = a3.x; As[buf][13][tid] = a3.y; As[buf][14][tid] = a3.z; As[buf][15][tid] = a3.w;
        Bs[buf][bc8 + 0][brow] = w0.x; Bs[buf][bc8 + 1][brow] = w0.y;
        Bs[buf][bc8 + 2][brow] = w0.z; Bs[buf][bc8 + 3][brow] = w0.w;
        Bs[buf][bc8 + 4][brow] = w1.x; Bs[buf][bc8 + 5][brow] = w1.y;
        Bs[buf][bc8 + 6][brow] = w1.z; Bs[buf][bc8 + 7][brow] = w1.w;
        __syncthreads();

        if (k0 + 16 < K) {
            a0 = *reinterpret_cast<const float4*>(Ap + k0 + 16);
            a1 = *reinterpret_cast<const float4*>(Ap + k0 + 20);
            a2 = *reinterpret_cast<const float4*>(Ap + k0 + 24);
            a3 = *reinterpret_cast<const float4*>(Ap + k0 + 28);
            w0 = *reinterpret_cast<const float4*>(Wp + k0 + 16);
            w1 = *reinterpret_cast<const float4*>(Wp + k0 + 20);
        }
#pragma unroll
        for (int k = 0; k < 16; k++) {
            float a[8], b[8];
            *reinterpret_cast<float4*>(&a[0]) = *reinterpret_cast<const float4*>(&As[buf][k][ty * 8]);
            *reinterpret_cast<float4*>(&a[4]) = *reinterpret_cast<const float4*>(&As[buf][k][ty * 8 + 4]);
            *reinterpret_cast<float4*>(&b[0]) = *reinterpret_cast<const float4*>(&Bs[buf][k][tx * 8]);
            *reinterpret_cast<float4*>(&b[4]) = *reinterpret_cast<const float4*>(&Bs[buf][k][tx * 8 + 4]);
#pragma unroll
            for (int i = 0; i < 8; i++)
#pragma unroll
                for (int j = 0; j < 8; j++)
                    acc[i][j] += a[i] * b[j];
        }
        buf ^= 1;
    }
    float4 bv0 = *reinterpret_cast<const float4*>(bias + n0 + tx * 8);
    float4 bv1 = *reinterpret_cast<const float4*>(bias + n0 + tx * 8 + 4);
#pragma unroll
    for (int i = 0; i < 8; i++) {
        float4 o0, o1;
        o0.x = fmaxf(acc[i][0] + bv0.x, 0.f);
        o0.y = fmaxf(acc[i][1] + bv0.y, 0.f);
        o0.z = fmaxf(acc[i][2] + bv0.z, 0.f);
        o0.w = fmaxf(acc[i][3] + bv0.w, 0.f);
        o1.x = fmaxf(acc[i][4] + bv1.x, 0.f);
        o1.y = fmaxf(acc[i][5] + bv1.y, 0.f);
        o1.z = fmaxf(acc[i][6] + bv1.z, 0.f);
        o1.w = fmaxf(acc[i][7] + bv1.w, 0.f);
        float* crow = C + (size_t)(m0 + ty * 8 + i) * N + n0 + tx * 8;
        *reinterpret_cast<float4*>(crow)     = o0;
        *reinterpret_cast<float4*>(crow + 4) = o1;
    }
}

// ---------------- max pools ----------------
__global__ void maxpool1_kernel() {
    int i = blockIdx.x * blockDim.x + threadIdx.x;   // < 2048*128
    int s = i >> 7, c = i & 127;
    const float* base = &g_bufC[(size_t)s * 32 * 128 + c];
    float v = base[0];
#pragma unroll
    for (int k = 1; k < 32; k++) v = fmaxf(v, base[(size_t)k * 128]);
    g_f1[i] = v;
}
__global__ void maxpool2_kernel() {
    int i = blockIdx.x * blockDim.x + threadIdx.x;   // < 512*256
    int s = i >> 8, c = i & 255;
    const float* base = &g_bufD[(size_t)s * 64 * 256 + c];
    float v = base[0];
#pragma unroll
    for (int k = 1; k < 64; k++) v = fmaxf(v, base[(size_t)k * 256]);
    g_f2[i] = v;
}
__global__ void finalmax_kernel(float* __restrict__ out) {
    int c = blockIdx.x * blockDim.x + threadIdx.x;
    if (c >= 1024) return;
    float v = g_bufC[c];
    for (int s = 1; s < 512; s++) v = fmaxf(v, g_bufC[(size_t)s * 1024 + c]);
    out[c] = v;
}

// ---------------- launch ----------------
extern "C" void kernel_launch(void* const* d_in, const int* in_sizes, int n_in,
                              void* d_out, int out_size) {
    const float* points = (const float*)d_in[0];
    const float* prop   = (const float*)d_in[1];

    // Input binding: runtime-detect tensor ordering (dict-interleaved vs signature).
    const float *w10, *w11, *w12, *b10, *b11, *b12;
    const float *w20, *w21, *w22, *b20, *b21, *b22;
    const float *w30, *w31, *w32, *b30, *b31, *b32;
    if (in_sizes[3] == 64) {
        w10 = (const float*)d_in[2];  b10 = (const float*)d_in[3];
        w11 = (const float*)d_in[4];  b11 = (const float*)d_in[5];
        w12 = (const float*)d_in[6];  b12 = (const float*)d_in[7];
        w20 = (const float*)d_in[8];  b20 = (const float*)d_in[9];
        w21 = (const float*)d_in[10]; b21 = (const float*)d_in[11];
        w22 = (const float*)d_in[12]; b22 = (const float*)d_in[13];
        w30 = (const float*)d_in[14]; b30 = (const float*)d_in[15];
        w31 = (const float*)d_in[16]; b31 = (const float*)d_in[17];
        w32 = (const float*)d_in[18]; b32 = (const float*)d_in[19];
    } else {
        w10 = (const float*)d_in[2];  w11 = (const float*)d_in[3];  w12 = (const float*)d_in[4];
        b10 = (const float*)d_in[5];  b11 = (const float*)d_in[6];  b12 = (const float*)d_in[7];
        w20 = (const float*)d_in[8];  w21 = (const float*)d_in[9];  w22 = (const float*)d_in[10];
        b20 = (const float*)d_in[11]; b21 = (const float*)d_in[12]; b22 = (const float*)d_in[13];
        w30 = (const float*)d_in[14]; w31 = (const float*)d_in[15]; w32 = (const float*)d_in[16];
        b30 = (const float*)d_in[17]; b31 = (const float*)d_in[18]; b32 = (const float*)d_in[19];
    }
    float* out = (float*)d_out;

    float *h0, *bufA, *bufB, *bufC, *bufD, *wp, *a3;
    cudaGetSymbolAddress((void**)&h0,    g_h0);
    cudaGetSymbolAddress((void**)&bufA,  g_bufA);
    cudaGetSymbolAddress((void**)&bufB,  g_bufB);
    cudaGetSymbolAddress((void**)&bufC,  g_bufC);
    cudaGetSymbolAddress((void**)&bufD,  g_bufD);
    cudaGetSymbolAddress((void**)&wp,    g_wp);
    cudaGetSymbolAddress((void**)&a3,    g_a3);

    cudaFuncSetAttribute(mega_kernel,
                         cudaFuncAttributeMaxDynamicSharedMemorySize, 65536);

    // stage 0 (fused prep + weight padding; zeroes FPS1 packets + center tags)
    prep_padw_kernel<<<(PADW_TOTAL + 255) / 256, 256>>>(points, prop, w10, w20, w30);

    // fps1 || bq1 (flag-overlapped) || fps2 — one resident mega-launch
    mega_kernel<<<73, 1024, 65536>>>();

    group1_bq2_kernel<<<320, 256>>>();               // group1 || bq2
    {
        dim3 g1(65536 / 128, 1);  gemm_bias_relu<<<g1, 128>>>(h0,   wp + WP1_OFF, b10, bufA, 65536, 64, 16);
        dim3 g2(65536 / 128, 1);  gemm_bias_relu<<<g2, 128>>>(bufA, w11,          b11, bufB, 65536, 64, 64);
        dim3 g3(65536 / 128, 2);  gemm_bias_relu<<<g3, 128>>>(bufB, w12,          b12, bufC, 65536, 128, 64);
    }
    maxpool1_kernel<<<(NP1 * 128 + 255) / 256, 256>>>();

    // SA2
    group2_kernel<<<(NP2 * NS2 + 255) / 256, 256>>>();
    {
        dim3 g4(32768 / 128, 2);  gemm_bias_relu<<<g4, 128>>>(bufC, wp + WP2_OFF, b20, bufA, 32768, 128, 144);
        dim3 g5(32768 / 128, 2);  gemm_bias_relu<<<g5, 128>>>(bufA, w21,          b21, bufB, 32768, 128, 128);
        dim3 g6(32768 / 128, 4);  gemm_bias_relu<<<g6, 128>>>(bufB, w22,          b22, bufD, 32768, 256, 128);
    }
    maxpool2_kernel<<<(NP2 * 256 + 255) / 256, 256>>>();

    // SA3
    a3_kernel<<<(NP2 * 272 + 255) / 256, 256>>>();
    {
        dim3 g7(512 / 128, 4);    gemm_bias_relu<<<g7, 128>>>(a3,   wp + WP3_OFF, b30, bufA, 512, 256, 272);
        dim3 g8(512 / 128, 8);    gemm_bias_relu<<<g8, 128>>>(bufA, w31,          b31, bufB, 512, 512, 256);
        dim3 g9(512 / 128, 16);   gemm_bias_relu<<<g9, 128>>>(bufB, w32,          b32, bufC, 512, 1024, 512);
    }
    finalmax_kernel<<<4, 256>>>(out);
}